// round 1
// baseline (speedup 1.0000x reference)
#include <cuda_runtime.h>
#include <math.h>

// ---------------- problem constants (fixed by the dataset) ----------------
#define N0C 50000
#define N1C 200000   // also max rows per level -> used as per-head stride
#define N2C 100000
#define FINC 500
#define DC 64
#define EMAXC 1000000  // max nnz per head (L1a/L1b)

// ---------------- device scratch (no allocations allowed) ----------------
__device__ unsigned g_bits[N0C * 16];          // bit-packed binarized X0 (512 bits/node)
__device__ float    g_Wp[3 * 512 * 128];       // per-level packed [512 x 128] weights (2 heads)
__device__ float    g_bp[3 * 128];             // per-level packed bias
__device__ float    g_Xh0[(size_t)N0C * 128];
__device__ float    g_Xh1[(size_t)N1C * 128];
__device__ float    g_Xh2[(size_t)N2C * 128];
__device__ float    g_s1[6 * N1C];
__device__ float    g_s2[6 * N1C];
__device__ unsigned g_mx[6 * N1C];             // ordered-encoded float max
__device__ float    g_z [6 * N1C];
__device__ float    g_e [6 * EMAXC];
__device__ float    g_H0[(size_t)N0C * 64];
__device__ float    g_H1[(size_t)N1C * 64];
__device__ float    g_H2[(size_t)N2C * 64];
__device__ float    g_S1[(size_t)N0C * 64];    // spmm(B1, H1)
__device__ float    g_U [(size_t)N1C * 64];    // spmm(B2, H2)
__device__ float    g_V [(size_t)N0C * 64];    // spmm(B1, U)
__device__ float    g_tsum[N0C];               // rowsum of B1 values

// ------------- helpers: order-preserving float<->uint for atomicMax -------
__device__ __forceinline__ unsigned ford(float f) {
    unsigned u = __float_as_uint(f);
    return (u & 0x80000000u) ? ~u : (u | 0x80000000u);
}
__device__ __forceinline__ float forddec(unsigned u) {
    return (u & 0x80000000u) ? __uint_as_float(u & 0x7fffffffu)
                             : __uint_as_float(~u);
}

// ---------------- 1) binarize + bitpack X0 ----------------
__global__ void pack_bits_kernel(const float* __restrict__ X0, int n0) {
    int lane = threadIdx.x & 31;
    int node = (blockIdx.x * blockDim.x + threadIdx.x) >> 5;
    if (node >= n0) return;
    const float* row = X0 + (size_t)node * FINC;
#pragma unroll
    for (int wd = 0; wd < 16; wd++) {
        int bi = wd * 32 + lane;
        float f = (bi < FINC) ? row[bi] : 0.f;
        unsigned m = __ballot_sync(0xffffffffu, f != 0.f);
        if (lane == 0) g_bits[node * 16 + wd] = m;
    }
}

// ---------------- 2) pack W,b: [6,500,64] -> per level [512,128] ----------
__global__ void pack_W_kernel(const float* __restrict__ W, const float* __restrict__ b) {
    int idx = blockIdx.x * blockDim.x + threadIdx.x;
    if (idx >= 3 * 512 * 128) return;
    int lev = idx / (512 * 128);
    int rem = idx - lev * (512 * 128);
    int k = rem >> 7;
    int j = rem & 127;
    int head = lev * 2 + (j >> 6);
    int jj = j & 63;
    g_Wp[idx] = (k < FINC) ? W[((size_t)head * FINC + k) * DC + jj] : 0.f;
    if (k == 0) g_bp[lev * 128 + j] = b[head * DC + jj];
}

// ---------------- 3) binary-A GEMM: out[n,128] = bits(A) @ Wp + bp --------
// mode 0: A row = bits[node r]; mode 1: AND of edge endpoints; mode 2: AND of 3
__global__ void __launch_bounds__(256, 2)
gemm_bits_kernel(int lev, int mode, int n, const int* __restrict__ elem,
                 float* __restrict__ out) {
    __shared__ float sW[32 * 128];
    const float* Wp = g_Wp + (size_t)lev * 512 * 128;
    int t = threadIdx.x;
    int tr = t >> 4, tc = t & 15;
    int m0 = blockIdx.x * 64;

    int rows[4], ia[4], ib[4], ic[4];
#pragma unroll
    for (int i = 0; i < 4; i++) {
        int r = m0 + tr + i * 16;
        int rr = (r < n) ? r : 0;
        rows[i] = (r < n) ? r : -1;
        if (mode == 0) { ia[i] = rr; ib[i] = rr; ic[i] = rr; }
        else if (mode == 1) { ia[i] = elem[2 * rr]; ib[i] = elem[2 * rr + 1]; ic[i] = ia[i]; }
        else { ia[i] = elem[3 * rr]; ib[i] = elem[3 * rr + 1]; ic[i] = elem[3 * rr + 2]; }
    }

    float acc[4][8];
#pragma unroll
    for (int i = 0; i < 4; i++)
#pragma unroll
        for (int c = 0; c < 8; c++) acc[i][c] = 0.f;

    for (int w = 0; w < 16; w++) {
        const float4* src = (const float4*)(Wp + (size_t)w * 4096);
        float4* dst = (float4*)sW;
#pragma unroll
        for (int q = 0; q < 4; q++) dst[q * 256 + t] = src[q * 256 + t];
        __syncthreads();

        unsigned a[4];
#pragma unroll
        for (int i = 0; i < 4; i++) {
            unsigned wa = g_bits[ia[i] * 16 + w];
            if (mode >= 1) wa &= g_bits[ib[i] * 16 + w];
            if (mode == 2) wa &= g_bits[ic[i] * 16 + w];
            a[i] = wa;
        }
        const float4* sv = (const float4*)sW;
#pragma unroll
        for (int kk = 0; kk < 32; kk++) {
            float4 w0 = sv[kk * 32 + tc * 2];
            float4 w1 = sv[kk * 32 + tc * 2 + 1];
#pragma unroll
            for (int i = 0; i < 4; i++) {
                unsigned msk = (unsigned)(-(int)((a[i] >> kk) & 1u));
                float av = __uint_as_float(0x3f800000u & msk);
                acc[i][0] = fmaf(av, w0.x, acc[i][0]);
                acc[i][1] = fmaf(av, w0.y, acc[i][1]);
                acc[i][2] = fmaf(av, w0.z, acc[i][2]);
                acc[i][3] = fmaf(av, w0.w, acc[i][3]);
                acc[i][4] = fmaf(av, w1.x, acc[i][4]);
                acc[i][5] = fmaf(av, w1.y, acc[i][5]);
                acc[i][6] = fmaf(av, w1.z, acc[i][6]);
                acc[i][7] = fmaf(av, w1.w, acc[i][7]);
            }
        }
        __syncthreads();
    }

    const float* bp = g_bp + lev * 128 + tc * 8;
    float bias[8];
#pragma unroll
    for (int c = 0; c < 8; c++) bias[c] = bp[c];
#pragma unroll
    for (int i = 0; i < 4; i++) {
        if (rows[i] < 0) continue;
        float* o = out + (size_t)rows[i] * 128 + tc * 8;
#pragma unroll
        for (int c = 0; c < 8; c++) o[c] = acc[i][c] + bias[c];
    }
}

// ---------------- 4) per-row attention logits s1,s2 (both heads) ----------
__global__ void s_kernel(int lev, int n, const float* __restrict__ Xh,
                         const float* __restrict__ a1w, const float* __restrict__ a1b,
                         const float* __restrict__ a2w, const float* __restrict__ a2b) {
    int gw = (blockIdx.x * blockDim.x + threadIdx.x) >> 5;
    int lane = threadIdx.x & 31;
    if (gw >= n) return;
    float4 h = *(const float4*)(Xh + (size_t)gw * 128 + lane * 4);
    int head = 2 * lev + (lane >> 4);
    int off = head * 64 + (lane & 15) * 4;
    float4 w1 = *(const float4*)(a1w + off);
    float4 w2 = *(const float4*)(a2w + off);
    float p1 = h.x * w1.x + h.y * w1.y + h.z * w1.z + h.w * w1.w;
    float p2 = h.x * w2.x + h.y * w2.y + h.z * w2.z + h.w * w2.w;
#pragma unroll
    for (int o = 8; o >= 1; o >>= 1) {
        p1 += __shfl_xor_sync(0xffffffffu, p1, o);
        p2 += __shfl_xor_sync(0xffffffffu, p2, o);
    }
    if ((lane & 15) == 0) {
        g_s1[head * N1C + gw] = p1 + a1b[head];
        g_s2[head * N1C + gw] = p2 + a2b[head];
    }
}

// ---------------- 5) segment max of s2[c] over rows ----------------------
__global__ void att_max_kernel(const int* __restrict__ idx, int nnz, int hA, int hB) {
    int j = blockIdx.x * blockDim.x + threadIdx.x;
    if (j >= nnz) return;
    int r = idx[j], c = idx[nnz + j];
    atomicMax(&g_mx[hA * N1C + r], ford(g_s2[hA * N1C + c]));
    if (hB >= 0) atomicMax(&g_mx[hB * N1C + r], ford(g_s2[hB * N1C + c]));
}

// ---------------- 6) e = exp(s2[c]-mx[r]); z[r] += e ----------------------
__global__ void att_sumexp_kernel(const int* __restrict__ idx, int nnz, int hA, int hB) {
    int j = blockIdx.x * blockDim.x + threadIdx.x;
    if (j >= nnz) return;
    int r = idx[j], c = idx[nnz + j];
    float eA = expf(g_s2[hA * N1C + c] - forddec(g_mx[hA * N1C + r]));
    g_e[(size_t)hA * EMAXC + j] = eA;
    atomicAdd(&g_z[hA * N1C + r], eA);
    if (hB >= 0) {
        float eB = expf(g_s2[hB * N1C + c] - forddec(g_mx[hB * N1C + r]));
        g_e[(size_t)hB * EMAXC + j] = eB;
        atomicAdd(&g_z[hB * N1C + r], eB);
    }
}

// ---------------- 7) scatter att*h[c] into H[r] ----------------------------
// dual-head variant (both heads share the same COO index array)
__global__ void att_scatter2_kernel(const int* __restrict__ idx, int nnz, int hA, int hB,
                                    const float* __restrict__ Xh, float* __restrict__ H) {
    int gw = (blockIdx.x * blockDim.x + threadIdx.x) >> 5;
    int lane = threadIdx.x & 31;
    if (gw >= nnz) return;
    int r = idx[gw], c = idx[nnz + gw];
    float wA = g_e[(size_t)hA * EMAXC + gw] / g_z[hA * N1C + r];
    float wB = g_e[(size_t)hB * EMAXC + gw] / g_z[hB * N1C + r];
    float2 hAv = *(const float2*)(Xh + (size_t)c * 128 + lane * 2);
    float2 hBv = *(const float2*)(Xh + (size_t)c * 128 + 64 + lane * 2);
    float2 v;
    v.x = wA * hAv.x + wB * hBv.x;
    v.y = wA * hAv.y + wB * hBv.y;
    atomicAdd((float2*)(H + (size_t)r * 64 + lane * 2), v);
}

__global__ void att_scatter1_kernel(const int* __restrict__ idx, int nnz, int head,
                                    const float* __restrict__ Xh, float* __restrict__ H) {
    int gw = (blockIdx.x * blockDim.x + threadIdx.x) >> 5;
    int lane = threadIdx.x & 31;
    if (gw >= nnz) return;
    int r = idx[gw], c = idx[nnz + gw];
    float wv = g_e[(size_t)head * EMAXC + gw] / g_z[head * N1C + r];
    int hoff = (head & 1) * 64;
    float2 hv = *(const float2*)(Xh + (size_t)c * 128 + hoff + lane * 2);
    float2 v; v.x = wv * hv.x; v.y = wv * hv.y;
    atomicAdd((float2*)(H + (size_t)r * 64 + lane * 2), v);
}

// ---------------- 8) in-place PReLU -----------------------------------------
__global__ void prelu_kernel(float* __restrict__ buf, int n4, const float* __restrict__ pw) {
    int i = blockIdx.x * blockDim.x + threadIdx.x;
    if (i >= n4) return;
    float p = pw[0];
    float4 x = ((float4*)buf)[i];
    x.x = (x.x >= 0.f) ? x.x : p * x.x;
    x.y = (x.y >= 0.f) ? x.y : p * x.y;
    x.z = (x.z >= 0.f) ? x.z : p * x.z;
    x.w = (x.w >= 0.f) ? x.w : p * x.w;
    ((float4*)buf)[i] = x;
}

// ---------------- 9) COO spmm scatter: dst[r] += val * src[c] --------------
__global__ void spmm_kernel(const int* __restrict__ idx, const float* __restrict__ vals,
                            int nnz, const float* __restrict__ src,
                            float* __restrict__ dst, float* __restrict__ tsum) {
    int gw = (blockIdx.x * blockDim.x + threadIdx.x) >> 5;
    int lane = threadIdx.x & 31;
    if (gw >= nnz) return;
    int r = idx[gw], c = idx[nnz + gw];
    float val = vals[gw];
    float2 x = *(const float2*)(src + (size_t)c * 64 + lane * 2);
    float2 v; v.x = val * x.x; v.y = val * x.y;
    atomicAdd((float2*)(dst + (size_t)r * 64 + lane * 2), v);
    if (tsum != nullptr && lane == 0) atomicAdd(&tsum[r], val);
}

// ---------------- 10) final: out = (H0 + S1 + V@triW + tsum*trib)/3 --------
__global__ void __launch_bounds__(256)
final_kernel(const float* __restrict__ triW, const float* __restrict__ trib,
             float* __restrict__ out, int n0) {
    __shared__ float sT[64 * 64];
    int t = threadIdx.x;
#pragma unroll
    for (int q = 0; q < 16; q++) sT[q * 256 + t] = triW[q * 256 + t];
    __syncthreads();
    int gw = blockIdx.x * 8 + (t >> 5);
    int lane = t & 31;
    if (gw >= n0) return;
    float2 v = *(const float2*)(g_V + (size_t)gw * 64 + lane * 2);
    float2 o; o.x = 0.f; o.y = 0.f;
#pragma unroll
    for (int k = 0; k < 64; k++) {
        float vk = __shfl_sync(0xffffffffu, (k & 1) ? v.y : v.x, k >> 1);
        float2 tw = *(const float2*)(sT + k * 64 + lane * 2);
        o.x = fmaf(vk, tw.x, o.x);
        o.y = fmaf(vk, tw.y, o.y);
    }
    float2 h0 = *(const float2*)(g_H0 + (size_t)gw * 64 + lane * 2);
    float2 s1 = *(const float2*)(g_S1 + (size_t)gw * 64 + lane * 2);
    float ts = g_tsum[gw];
    float2 tb = *(const float2*)(trib + lane * 2);
    float2 r;
    r.x = (h0.x + s1.x + o.x + ts * tb.x) * (1.f / 3.f);
    r.y = (h0.y + s1.y + o.y + ts * tb.y) * (1.f / 3.f);
    *(float2*)(out + (size_t)gw * 64 + lane * 2) = r;
}

// ======================== host launcher ====================================
static inline void* symaddr(const void* sym) {
    void* p = nullptr;
    cudaGetSymbolAddress(&p, sym);
    return p;
}

extern "C" void kernel_launch(void* const* d_in, const int* in_sizes, int n_in,
                              void* d_out, int out_size) {
    const float* X0  = (const float*)d_in[0];
    const int*   E1  = (const int*)d_in[1];
    const int*   T2  = (const int*)d_in[2];
    const int*   L0  = (const int*)d_in[3];
    const int*   L1a = (const int*)d_in[4];
    const int*   L1b = (const int*)d_in[5];
    const int*   L2  = (const int*)d_in[6];
    const int*   B1i = (const int*)d_in[7];
    const float* B1v = (const float*)d_in[8];
    const int*   B2i = (const int*)d_in[9];
    const float* B2v = (const float*)d_in[10];
    const float* W   = (const float*)d_in[11];
    const float* b   = (const float*)d_in[12];
    const float* a1w = (const float*)d_in[13];
    const float* a1b = (const float*)d_in[14];
    const float* a2w = (const float*)d_in[15];
    const float* a2b = (const float*)d_in[16];
    const float* pw  = (const float*)d_in[17];
    const float* triW = (const float*)d_in[18];
    const float* trib = (const float*)d_in[19];

    int n0 = in_sizes[0] / FINC;
    int n1 = in_sizes[1] / 2;
    int n2 = in_sizes[2] / 3;
    int nnz0  = in_sizes[3] / 2;
    int nnz1a = in_sizes[4] / 2;
    int nnz1b = in_sizes[5] / 2;
    int nnz2  = in_sizes[6] / 2;
    int nb1 = in_sizes[8];
    int nb2 = in_sizes[10];

    float* Xh0 = (float*)symaddr(g_Xh0);
    float* Xh1 = (float*)symaddr(g_Xh1);
    float* Xh2 = (float*)symaddr(g_Xh2);
    float* H0  = (float*)symaddr(g_H0);
    float* H1  = (float*)symaddr(g_H1);
    float* H2  = (float*)symaddr(g_H2);
    float* S1  = (float*)symaddr(g_S1);
    float* U   = (float*)symaddr(g_U);
    float* V   = (float*)symaddr(g_V);
    float* tsum = (float*)symaddr(g_tsum);
    void*  mx  = symaddr(g_mx);
    void*  z   = symaddr(g_z);

    // zero accumulators (graph-capturable memset nodes)
    cudaMemsetAsync(H0, 0, sizeof(float) * (size_t)n0 * 64);
    cudaMemsetAsync(H1, 0, sizeof(float) * (size_t)n1 * 64);
    cudaMemsetAsync(H2, 0, sizeof(float) * (size_t)n2 * 64);
    cudaMemsetAsync(S1, 0, sizeof(float) * (size_t)n0 * 64);
    cudaMemsetAsync(U,  0, sizeof(float) * (size_t)n1 * 64);
    cudaMemsetAsync(V,  0, sizeof(float) * (size_t)n0 * 64);
    cudaMemsetAsync(tsum, 0, sizeof(float) * (size_t)n0);
    cudaMemsetAsync(mx, 0, sizeof(unsigned) * 6 * N1C);   // 0 == encoded minimum
    cudaMemsetAsync(z,  0, sizeof(float) * 6 * N1C);

    // 1) pack bits, 2) pack weights
    pack_bits_kernel<<<(n0 * 32 + 255) / 256, 256>>>(X0, n0);
    pack_W_kernel<<<(3 * 512 * 128 + 255) / 256, 256>>>(W, b);

    // 3) three binary-A GEMMs (two heads packed per level)
    gemm_bits_kernel<<<(n0 + 63) / 64, 256>>>(0, 0, n0, E1, Xh0);
    gemm_bits_kernel<<<(n1 + 63) / 64, 256>>>(1, 1, n1, E1, Xh1);
    gemm_bits_kernel<<<(n2 + 63) / 64, 256>>>(2, 2, n2, T2, Xh2);

    // 4) logits
    s_kernel<<<(n0 * 32 + 255) / 256, 256>>>(0, n0, Xh0, a1w, a1b, a2w, a2b);
    s_kernel<<<(n1 * 32 + 255) / 256, 256>>>(1, n1, Xh1, a1w, a1b, a2w, a2b);
    s_kernel<<<(n2 * 32 + 255) / 256, 256>>>(2, n2, Xh2, a1w, a1b, a2w, a2b);

    // 5) segment max
    att_max_kernel<<<(nnz0 + 255) / 256, 256>>>(L0, nnz0, 0, 1);
    att_max_kernel<<<(nnz1a + 255) / 256, 256>>>(L1a, nnz1a, 2, -1);
    att_max_kernel<<<(nnz1b + 255) / 256, 256>>>(L1b, nnz1b, 3, -1);
    att_max_kernel<<<(nnz2 + 255) / 256, 256>>>(L2, nnz2, 4, 5);

    // 6) exp + segment sum
    att_sumexp_kernel<<<(nnz0 + 255) / 256, 256>>>(L0, nnz0, 0, 1);
    att_sumexp_kernel<<<(nnz1a + 255) / 256, 256>>>(L1a, nnz1a, 2, -1);
    att_sumexp_kernel<<<(nnz1b + 255) / 256, 256>>>(L1b, nnz1b, 3, -1);
    att_sumexp_kernel<<<(nnz2 + 255) / 256, 256>>>(L2, nnz2, 4, 5);

    // 7) attention-weighted scatter (warp per nnz)
    att_scatter2_kernel<<<(nnz0 + 7) / 8, 256>>>(L0, nnz0, 0, 1, Xh0, H0);
    att_scatter1_kernel<<<(nnz1a + 7) / 8, 256>>>(L1a, nnz1a, 2, Xh1, H1);
    att_scatter1_kernel<<<(nnz1b + 7) / 8, 256>>>(L1b, nnz1b, 3, Xh1, H1);
    att_scatter2_kernel<<<(nnz2 + 7) / 8, 256>>>(L2, nnz2, 4, 5, Xh2, H2);

    // 8) PReLU
    prelu_kernel<<<((n0 * 64 / 4) + 255) / 256, 256>>>(H0, n0 * 16, pw);
    prelu_kernel<<<((n1 * 64 / 4) + 255) / 256, 256>>>(H1, n1 * 16, pw);
    prelu_kernel<<<((n2 * 64 / 4) + 255) / 256, 256>>>(H2, n2 * 16, pw);

    // 9) boundary spmms. Note: spmm(B1, U@triW + trib) == spmm(B1,U)@triW + rowsum(B1)*trib,
    //    so the 64x64 GEMM moves to n0 rows and fuses into the final kernel.
    spmm_kernel<<<(nb1 + 7) / 8, 256>>>(B1i, B1v, nb1, H1, S1, tsum);
    spmm_kernel<<<(nb2 + 7) / 8, 256>>>(B2i, B2v, nb2, H2, U, nullptr);
    spmm_kernel<<<(nb1 + 7) / 8, 256>>>(B1i, B1v, nb1, U, V, nullptr);

    // 10) combine
    final_kernel<<<(n0 + 7) / 8, 256>>>(triW, trib, (float*)d_out, n0);
}

// round 5
// speedup vs baseline: 1.9766x; 1.9766x over previous
#include <cuda_runtime.h>
#include <cuda_bf16.h>
#include <math.h>
#include <stdint.h>

// tcgen05 only exists in the arch-specific (sm_103a) device pass.
#if defined(__CUDA_ARCH_FEAT_SM103_ALL) || \
    (defined(__CUDA_ARCH_SPECIFIC__) && (__CUDA_ARCH__ == 1030))
#define HAS_TC 1
#else
#define HAS_TC 0
#endif

// ---------------- problem constants (fixed by the dataset) ----------------
#define N0C 50000
#define N1C 200000   // also max rows per level -> used as per-head stride
#define N2C 100000
#define FINC 500
#define DC 64
#define EMAXC 1000000  // max nnz per head (L1a/L1b)

// ---------------- device scratch (no allocations allowed) ----------------
__device__ unsigned g_bits[N0C * 16];          // bit-packed binarized X0 (512 bits/node)
__device__ __align__(16) unsigned char g_Wt[3 * 2 * 8 * 16384]; // [lev][split][chunk] 128x64 bf16 SW128
__device__ float    g_Wp[3 * 512 * 128];       // fp32 packed weights (SIMT fallback)
__device__ float    g_bp[3 * 128];             // per-level packed bias
__device__ float    g_Xh0[(size_t)N0C * 128];
__device__ float    g_Xh1[(size_t)N1C * 128];
__device__ float    g_Xh2[(size_t)N2C * 128];
__device__ float    g_s1[6 * N1C];
__device__ float    g_s2[6 * N1C];
__device__ unsigned g_mx[6 * N1C];             // ordered-encoded float max
__device__ float    g_z [6 * N1C];
__device__ float    g_e [6 * EMAXC];
__device__ float    g_H0[(size_t)N0C * 64];
__device__ float    g_H1[(size_t)N1C * 64];
__device__ float    g_H2[(size_t)N2C * 64];
__device__ float    g_S1[(size_t)N0C * 64];    // spmm(B1, H1)
__device__ float    g_U [(size_t)N1C * 64];    // spmm(B2, H2)
__device__ float    g_V [(size_t)N0C * 64];    // spmm(B1, U)
__device__ float    g_tsum[N0C];               // rowsum of B1 values

// ---------------- PTX helpers (sm_103a-only emission) ----------------
__device__ __forceinline__ uint32_t smem_u32(const void* p) {
    uint32_t a;
    asm("{ .reg .u64 t; cvta.to.shared.u64 t, %1; cvt.u32.u64 %0, t; }" : "=r"(a) : "l"(p));
    return a;
}
#if HAS_TC
__device__ __forceinline__ uint32_t elect_one() {
    uint32_t pred;
    asm volatile("{\n\t.reg .pred p;\n\telect.sync _|p, 0xFFFFFFFF;\n\tselp.b32 %0, 1, 0, p;\n\t}" : "=r"(pred));
    return pred;
}
#define MBAR_INIT(addr, cnt) \
    asm volatile("mbarrier.init.shared.b64 [%0], %1;" :: "r"((uint32_t)(addr)), "r"((uint32_t)(cnt)) : "memory")
#define MBAR_WAIT(addr, par) do { \
    uint32_t _m = (uint32_t)(addr); uint32_t _p = (uint32_t)(par); uint32_t _d; \
    asm volatile("{\n\t.reg .pred p;\n\tmbarrier.try_wait.parity.acquire.cta.shared::cta.b64 p, [%1], %2;\n\tselp.b32 %0, 1, 0, p;\n\t}" \
        : "=r"(_d) : "r"(_m), "r"(_p) : "memory"); \
    if (!_d) { \
        asm volatile("{\n\t.reg .pred P1;\n\tWL_%=:\n\tmbarrier.try_wait.parity.acquire.cta.shared::cta.b64 P1, [%0], %1, 0x989680;\n\t@P1 bra.uni WD_%=;\n\tbra.uni WL_%=;\n\tWD_%=:\n\t}" \
            :: "r"(_m), "r"(_p) : "memory"); \
    } } while (0)
#define TC_ALLOC(sa, n)   asm volatile("tcgen05.alloc.cta_group::1.sync.aligned.shared::cta.b32 [%0], %1;" :: "r"((uint32_t)(sa)), "r"((uint32_t)(n)) : "memory")
#define TC_DEALLOC(t, n)  asm volatile("tcgen05.dealloc.cta_group::1.sync.aligned.b32 %0, %1;" :: "r"(t), "r"((uint32_t)(n)))
#define TC_COMMIT(mb)     asm volatile("tcgen05.commit.cta_group::1.mbarrier::arrive::one.shared::cluster.b64 [%0];" :: "r"((uint32_t)(mb)) : "memory")
#define TC_FENCE_AFTER()  asm volatile("tcgen05.fence::after_thread_sync;" ::: "memory")
#define TC_FENCE_BEFORE() asm volatile("tcgen05.fence::before_thread_sync;" ::: "memory")
#define TC_WAIT_LD()      asm volatile("tcgen05.wait::ld.sync.aligned;" ::: "memory")
#define FENCE_ASYNC()     asm volatile("fence.proxy.async.shared::cta;" ::: "memory")
#define TC_LD_X32(r, ta) \
    asm volatile("tcgen05.ld.sync.aligned.32x32b.x32.b32 " \
        "{%0, %1, %2, %3, %4, %5, %6, %7, %8, %9, %10, %11, %12, %13, %14, %15, " \
        " %16, %17, %18, %19, %20, %21, %22, %23, %24, %25, %26, %27, %28, %29, %30, %31}, [%32];" \
        : "=r"((r)[0]),  "=r"((r)[1]),  "=r"((r)[2]),  "=r"((r)[3]), \
          "=r"((r)[4]),  "=r"((r)[5]),  "=r"((r)[6]),  "=r"((r)[7]), \
          "=r"((r)[8]),  "=r"((r)[9]),  "=r"((r)[10]), "=r"((r)[11]), \
          "=r"((r)[12]), "=r"((r)[13]), "=r"((r)[14]), "=r"((r)[15]), \
          "=r"((r)[16]), "=r"((r)[17]), "=r"((r)[18]), "=r"((r)[19]), \
          "=r"((r)[20]), "=r"((r)[21]), "=r"((r)[22]), "=r"((r)[23]), \
          "=r"((r)[24]), "=r"((r)[25]), "=r"((r)[26]), "=r"((r)[27]), \
          "=r"((r)[28]), "=r"((r)[29]), "=r"((r)[30]), "=r"((r)[31]) \
        : "r"(ta))

static constexpr uint64_t DESC_BASE_SW128 =
    (uint64_t(2) << 61) | (uint64_t(1) << 46) | (uint64_t(64) << 32) | (uint64_t(1) << 16);
#define MAKE_DESC(a) (DESC_BASE_SW128 | ((uint64_t)((a) >> 4) & 0x3FFF))

// idesc: dtype F32, atype/btype BF16, N=64, M=128 (example-verified shape)
#define MMA_IDESC_N64 ((1u << 4) | (1u << 7) | (1u << 10) | ((64u / 8u) << 17) | ((128u / 16u) << 24))

__device__ __forceinline__ void mma_f16_ss(uint32_t d, uint64_t a, uint64_t b, bool en) {
    uint32_t e = en ? 1u : 0u;
    asm volatile(
        "{\n\t.reg .pred p;\n\tsetp.ne.u32 p, %5, 0;\n\t"
        "tcgen05.mma.cta_group::1.kind::f16 [%0], %1, %2, %3, {%4, %4, %4, %4}, p;\n\t}"
        :: "r"(d), "l"(a), "l"(b), "r"(MMA_IDESC_N64), "r"(0u), "r"(e)
        : "memory");
}
#endif  // HAS_TC

// ------------- helpers: order-preserving float<->uint for atomicMax -------
__device__ __forceinline__ unsigned ford(float f) {
    unsigned u = __float_as_uint(f);
    return (u & 0x80000000u) ? ~u : (u | 0x80000000u);
}
__device__ __forceinline__ float forddec(unsigned u) {
    return (u & 0x80000000u) ? __uint_as_float(u & 0x7fffffffu)
                             : __uint_as_float(~u);
}

// ---------------- 1) binarize + bitpack X0 ----------------
__global__ void pack_bits_kernel(const float* __restrict__ X0, int n0) {
    int lane = threadIdx.x & 31;
    int node = (blockIdx.x * blockDim.x + threadIdx.x) >> 5;
    if (node >= n0) return;
    const float* row = X0 + (size_t)node * FINC;
#pragma unroll
    for (int wd = 0; wd < 16; wd++) {
        int bi = wd * 32 + lane;
        float f = (bi < FINC) ? row[bi] : 0.f;
        unsigned m = __ballot_sync(0xffffffffu, f != 0.f);
        if (lane == 0) g_bits[node * 16 + wd] = m;
    }
}

// ---------------- 2a) pack W into hi/lo bf16 SW128 tiles + bias -----------
__global__ void pack_Wt_kernel(const float* __restrict__ W, const float* __restrict__ b) {
    int idx = blockIdx.x * blockDim.x + threadIdx.x;
    if (idx >= 3 * 8 * 128 * 64) return;
    int kk = idx & 63;
    int n = (idx >> 6) & 127;
    int chunk = (idx >> 13) & 7;
    int lev = idx >> 16;
    int head = lev * 2 + (n >> 6);
    int jj = n & 63;
    int k = chunk * 64 + kk;
    float w = (k < FINC) ? W[((size_t)head * FINC + k) * DC + jj] : 0.f;
    __nv_bfloat16 hi = __float2bfloat16(w);
    __nv_bfloat16 lo = __float2bfloat16(w - __bfloat162float(hi));
    unsigned off = n * 128 + kk * 2;
    unsigned sw = off ^ ((off >> 3) & 0x70);
    size_t base_hi = (((size_t)lev * 2 + 0) * 8 + chunk) * 16384;
    size_t base_lo = (((size_t)lev * 2 + 1) * 8 + chunk) * 16384;
    *(__nv_bfloat16*)(g_Wt + base_hi + sw) = hi;
    *(__nv_bfloat16*)(g_Wt + base_lo + sw) = lo;
    if (k == 0) g_bp[lev * 128 + n] = b[head * DC + jj];
}

// ---------------- 2b) pack W fp32 [512 x 128] per level (fallback) --------
__global__ void pack_W_kernel(const float* __restrict__ W) {
    int idx = blockIdx.x * blockDim.x + threadIdx.x;
    if (idx >= 3 * 512 * 128) return;
    int lev = idx / (512 * 128);
    int rem = idx - lev * (512 * 128);
    int k = rem >> 7;
    int j = rem & 127;
    int head = lev * 2 + (j >> 6);
    int jj = j & 63;
    g_Wp[idx] = (k < FINC) ? W[((size_t)head * FINC + k) * DC + jj] : 0.f;
}

// ---------------- 3) feature GEMM: Xh[tile] = bits(A) @ W + bias ----------
// SMEM layout (dynamic, single-buffered, example-matching synchronous MMA)
#define SM_A    0        // 16384 (A tile, SW128, 128x64 bf16)
#define SM_B    16384    // 32768 (B: hi tile 16K + lo tile 16K; each 128 rows x 128B)
#define SM_BITS 49152    // 128 x 16 words (8192)
#define SM_IDS  57344    // 128 x 3 ints (1536)
#define SM_BIAS 58880    // 128 floats (512)
#define SM_LUT  59392    // 16 x uint2 (128)
#define SM_PTR  59520    // tmem pointer
#define SM_MBAR 59528    // 1 mbarrier
// padded so exactly ONE CTA per SM is resident -> no concurrent TMEM allocs
#define SMEM_TOTAL (120 * 1024)

#define TMEM_COLS 512

__global__ void __launch_bounds__(256) __cluster_dims__(1, 1, 1)
mma_feat_kernel(int lev, int mode, int n, const int* __restrict__ elem,
                float* __restrict__ out) {
    extern __shared__ char smem[];
    int t = threadIdx.x;
    int tile0 = blockIdx.x * 128;

    // ---- common prologue: ids, bias, bits ----
    if (t < 128) {
        int gr = tile0 + t; if (gr >= n) gr = n - 1;
        int a, bb, c;
        if (mode == 0)      { a = gr; bb = gr; c = gr; }
        else if (mode == 1) { a = elem[2 * gr]; bb = elem[2 * gr + 1]; c = a; }
        else                { a = elem[3 * gr]; bb = elem[3 * gr + 1]; c = elem[3 * gr + 2]; }
        int* ids = (int*)(smem + SM_IDS);
        ids[t * 3] = a; ids[t * 3 + 1] = bb; ids[t * 3 + 2] = c;
        ((float*)(smem + SM_BIAS))[t] = g_bp[lev * 128 + t];
    }
    __syncthreads();
    {
        const int* ids = (const int*)(smem + SM_IDS);
        unsigned* sbits = (unsigned*)(smem + SM_BITS);
        for (int i = t; i < 128 * 16; i += 256) {
            int row = i >> 4, w = i & 15;
            unsigned v = g_bits[ids[row * 3] * 16 + w];
            if (mode >= 1) v &= g_bits[ids[row * 3 + 1] * 16 + w];
            if (mode == 2) v &= g_bits[ids[row * 3 + 2] * 16 + w];
            sbits[i] = v;
        }
    }

#if HAS_TC
    uint32_t sb = smem_u32(smem);
    int wid = t >> 5;
    int lane = t & 31;
    // test_mma.cu pattern: warp 0 allocates, other warps just skip (no relinquish)
    if (wid == 0) {
        TC_ALLOC(sb + SM_PTR, TMEM_COLS);
    }
    if (t == 0) MBAR_INIT(sb + SM_MBAR, 1);
    if (t < 16) {
        unsigned w0 = ((t & 1) ? 0x3f80u : 0u) | ((t & 2) ? 0x3f800000u : 0u);
        unsigned w1 = ((t & 4) ? 0x3f80u : 0u) | ((t & 8) ? 0x3f800000u : 0u);
        ((uint2*)(smem + SM_LUT))[t] = make_uint2(w0, w1);
    }
    __syncthreads();

    uint32_t tmem;
    asm volatile("ld.shared.b32 %0, [%1];" : "=r"(tmem) : "r"(sb + SM_PTR));

    const uint2* lut = (const uint2*)(smem + SM_LUT);
    const unsigned* sbits = (const unsigned*)(smem + SM_BITS);
    int arow = t >> 1, ahalf = t & 1;
    const unsigned char* wt = g_Wt + (size_t)lev * (2 * 8 * 16384);

    for (int c = 0; c < 8; c++) {
        // A synth: each thread emits 32 bf16 (half a row) for this k-chunk
        {
            unsigned bw = sbits[arow * 16 + 2 * c + ahalf];
            char* Abuf = smem + SM_A;
#pragma unroll
            for (int j = 0; j < 4; j++) {
                unsigned nib0 = (bw >> (j * 8)) & 15u;
                unsigned nib1 = (bw >> (j * 8 + 4)) & 15u;
                uint2 p0 = lut[nib0];
                uint2 p1 = lut[nib1];
                unsigned off = arow * 128 + ahalf * 64 + j * 16;
                unsigned sw = off ^ ((off >> 3) & 0x70);
                *(uint4*)(Abuf + sw) = make_uint4(p0.x, p0.y, p1.x, p1.y);
            }
        }
        // B copy: hi + lo tiles (pre-swizzled in global)
        {
            const uint4* srcHi = (const uint4*)(wt + (size_t)c * 16384);
            const uint4* srcLo = (const uint4*)(wt + (size_t)(8 + c) * 16384);
            uint4* dstB = (uint4*)(smem + SM_B);
#pragma unroll
            for (int q = 0; q < 4; q++) dstB[q * 256 + t] = srcHi[q * 256 + t];
#pragma unroll
            for (int q = 0; q < 4; q++) dstB[1024 + q * 256 + t] = srcLo[q * 256 + t];
        }
        FENCE_ASYNC();
        __syncthreads();

        if (wid == 0 && elect_one()) {
            uint64_t adesc  = MAKE_DESC(sb + SM_A);
            uint64_t bdescH = MAKE_DESC(sb + SM_B);
            uint64_t bdescL = MAKE_DESC(sb + SM_B + 16384);
            // N=64 halves: B rows [0,64) = head0, rows [64,128) = head1.
            // Row 64 starts at byte 8192 -> descriptor offset +512 (16B units).
#pragma unroll
            for (int ks = 0; ks < 4; ks++) {
                bool first = (c == 0 && ks == 0);
#pragma unroll
                for (int h = 0; h < 2; h++) {
                    mma_f16_ss(tmem + h * 64, adesc + ks * 2,
                               bdescH + h * 512 + ks * 2, !first);
                    mma_f16_ss(tmem + h * 64, adesc + ks * 2,
                               bdescL + h * 512 + ks * 2, true);
                }
            }
            TC_COMMIT(sb + SM_MBAR);
        }
        // synchronous: everyone waits for this chunk's MMAs before buffer reuse
        MBAR_WAIT(sb + SM_MBAR, c & 1);
        __syncthreads();
    }

    TC_FENCE_AFTER();

    // epilogue: warp -> (subpartition = wid&3 rows, colgroup = wid>>2)
    {
        int part = wid & 3, colg = wid >> 2;
        uint32_t d0[32], d1[32];
        TC_LD_X32(d0, tmem + colg * 64);
        TC_LD_X32(d1, tmem + colg * 64 + 32);
        TC_WAIT_LD();
        TC_FENCE_BEFORE();
        int gr = tile0 + part * 32 + lane;
        if (gr < n) {
            const float* bias = (const float*)(smem + SM_BIAS) + colg * 64;
            float* o = out + (size_t)gr * 128 + colg * 64;
#pragma unroll
            for (int j = 0; j < 8; j++) {
                float4 v;
                v.x = __uint_as_float(d0[j * 4 + 0]) + bias[j * 4 + 0];
                v.y = __uint_as_float(d0[j * 4 + 1]) + bias[j * 4 + 1];
                v.z = __uint_as_float(d0[j * 4 + 2]) + bias[j * 4 + 2];
                v.w = __uint_as_float(d0[j * 4 + 3]) + bias[j * 4 + 3];
                *(float4*)(o + j * 4) = v;
            }
#pragma unroll
            for (int j = 0; j < 8; j++) {
                float4 v;
                v.x = __uint_as_float(d1[j * 4 + 0]) + bias[32 + j * 4 + 0];
                v.y = __uint_as_float(d1[j * 4 + 1]) + bias[32 + j * 4 + 1];
                v.z = __uint_as_float(d1[j * 4 + 2]) + bias[32 + j * 4 + 2];
                v.w = __uint_as_float(d1[j * 4 + 3]) + bias[32 + j * 4 + 3];
                *(float4*)(o + 32 + j * 4) = v;
            }
        }
    }
    __syncthreads();
    if (wid == 0) TC_DEALLOC(tmem, TMEM_COLS);

#else  // ---------------- SIMT fallback (non-sm_103a pass) ----------------
    const float* Wp = g_Wp + (size_t)lev * 512 * 128;
    float* sW = (float*)(smem + SM_A);
    const unsigned* sbits = (const unsigned*)(smem + SM_BITS);
    int tr = t >> 4, tc = t & 15;
    for (int h = 0; h < 2; h++) {
        float acc[4][8];
#pragma unroll
        for (int i = 0; i < 4; i++)
#pragma unroll
            for (int c = 0; c < 8; c++) acc[i][c] = 0.f;
        for (int w = 0; w < 16; w++) {
            __syncthreads();
            const float4* src = (const float4*)(Wp + (size_t)w * 4096);
            float4* dst = (float4*)sW;
#pragma unroll
            for (int q = 0; q < 4; q++) dst[q * 256 + t] = src[q * 256 + t];
            __syncthreads();
            unsigned a[4];
#pragma unroll
            for (int i = 0; i < 4; i++)
                a[i] = sbits[(h * 64 + tr + i * 16) * 16 + w];
            const float4* sv = (const float4*)sW;
#pragma unroll
            for (int kk = 0; kk < 32; kk++) {
                float4 w0 = sv[kk * 32 + tc * 2];
                float4 w1 = sv[kk * 32 + tc * 2 + 1];
#pragma unroll
                for (int i = 0; i < 4; i++) {
                    unsigned msk = (unsigned)(-(int)((a[i] >> kk) & 1u));
                    float av = __uint_as_float(0x3f800000u & msk);
                    acc[i][0] = fmaf(av, w0.x, acc[i][0]);
                    acc[i][1] = fmaf(av, w0.y, acc[i][1]);
                    acc[i][2] = fmaf(av, w0.z, acc[i][2]);
                    acc[i][3] = fmaf(av, w0.w, acc[i][3]);
                    acc[i][4] = fmaf(av, w1.x, acc[i][4]);
                    acc[i][5] = fmaf(av, w1.y, acc[i][5]);
                    acc[i][6] = fmaf(av, w1.z, acc[i][6]);
                    acc[i][7] = fmaf(av, w1.w, acc[i][7]);
                }
            }
        }
        const float* bias = (const float*)(smem + SM_BIAS) + tc * 8;
#pragma unroll
        for (int i = 0; i < 4; i++) {
            int r = tile0 + h * 64 + tr + i * 16;
            if (r < n) {
                float* o = out + (size_t)r * 128 + tc * 8;
#pragma unroll
                for (int c = 0; c < 8; c++) o[c] = acc[i][c] + bias[c];
            }
        }
    }
#endif
}

// ---------------- 4) per-row attention logits s1,s2 (both heads) ----------
__global__ void s_kernel(int lev, int n, const float* __restrict__ Xh,
                         const float* __restrict__ a1w, const float* __restrict__ a1b,
                         const float* __restrict__ a2w, const float* __restrict__ a2b) {
    int gw = (blockIdx.x * blockDim.x + threadIdx.x) >> 5;
    int lane = threadIdx.x & 31;
    if (gw >= n) return;
    float4 h = *(const float4*)(Xh + (size_t)gw * 128 + lane * 4);
    int head = 2 * lev + (lane >> 4);
    int off = head * 64 + (lane & 15) * 4;
    float4 w1 = *(const float4*)(a1w + off);
    float4 w2 = *(const float4*)(a2w + off);
    float p1 = h.x * w1.x + h.y * w1.y + h.z * w1.z + h.w * w1.w;
    float p2 = h.x * w2.x + h.y * w2.y + h.z * w2.z + h.w * w2.w;
#pragma unroll
    for (int o = 8; o >= 1; o >>= 1) {
        p1 += __shfl_xor_sync(0xffffffffu, p1, o);
        p2 += __shfl_xor_sync(0xffffffffu, p2, o);
    }
    if ((lane & 15) == 0) {
        g_s1[head * N1C + gw] = p1 + a1b[head];
        g_s2[head * N1C + gw] = p2 + a2b[head];
    }
}

// ---------------- 5) segment max of s2[c] over rows ----------------------
__global__ void att_max_kernel(const int* __restrict__ idx, int nnz, int hA, int hB) {
    int j = blockIdx.x * blockDim.x + threadIdx.x;
    if (j >= nnz) return;
    int r = idx[j], c = idx[nnz + j];
    atomicMax(&g_mx[hA * N1C + r], ford(g_s2[hA * N1C + c]));
    if (hB >= 0) atomicMax(&g_mx[hB * N1C + r], ford(g_s2[hB * N1C + c]));
}

// ---------------- 6) e = exp(s2[c]-mx[r]); z[r] += e ----------------------
__global__ void att_sumexp_kernel(const int* __restrict__ idx, int nnz, int hA, int hB) {
    int j = blockIdx.x * blockDim.x + threadIdx.x;
    if (j >= nnz) return;
    int r = idx[j], c = idx[nnz + j];
    float eA = expf(g_s2[hA * N1C + c] - forddec(g_mx[hA * N1C + r]));
    g_e[(size_t)hA * EMAXC + j] = eA;
    atomicAdd(&g_z[hA * N1C + r], eA);
    if (hB >= 0) {
        float eB = expf(g_s2[hB * N1C + c] - forddec(g_mx[hB * N1C + r]));
        g_e[(size_t)hB * EMAXC + j] = eB;
        atomicAdd(&g_z[hB * N1C + r], eB);
    }
}

// ---------------- 7) scatter att*h[c] into H[r] ----------------------------
__global__ void att_scatter2_kernel(const int* __restrict__ idx, int nnz, int hA, int hB,
                                    const float* __restrict__ Xh, float* __restrict__ H) {
    int gw = (blockIdx.x * blockDim.x + threadIdx.x) >> 5;
    int lane = threadIdx.x & 31;
    if (gw >= nnz) return;
    int r = idx[gw], c = idx[nnz + gw];
    float wA = g_e[(size_t)hA * EMAXC + gw] / g_z[hA * N1C + r];
    float wB = g_e[(size_t)hB * EMAXC + gw] / g_z[hB * N1C + r];
    float2 hAv = *(const float2*)(Xh + (size_t)c * 128 + lane * 2);
    float2 hBv = *(const float2*)(Xh + (size_t)c * 128 + 64 + lane * 2);
    float2 v;
    v.x = wA * hAv.x + wB * hBv.x;
    v.y = wA * hAv.y + wB * hBv.y;
    atomicAdd((float2*)(H + (size_t)r * 64 + lane * 2), v);
}

__global__ void att_scatter1_kernel(const int* __restrict__ idx, int nnz, int head,
                                    const float* __restrict__ Xh, float* __restrict__ H) {
    int gw = (blockIdx.x * blockDim.x + threadIdx.x) >> 5;
    int lane = threadIdx.x & 31;
    if (gw >= nnz) return;
    int r = idx[gw], c = idx[nnz + gw];
    float wv = g_e[(size_t)head * EMAXC + gw] / g_z[head * N1C + r];
    int hoff = (head & 1) * 64;
    float2 hv = *(const float2*)(Xh + (size_t)c * 128 + hoff + lane * 2);
    float2 v; v.x = wv * hv.x; v.y = wv * hv.y;
    atomicAdd((float2*)(H + (size_t)r * 64 + lane * 2), v);
}

// ---------------- 8) in-place PReLU -----------------------------------------
__global__ void prelu_kernel(float* __restrict__ buf, int n4, const float* __restrict__ pw) {
    int i = blockIdx.x * blockDim.x + threadIdx.x;
    if (i >= n4) return;
    float p = pw[0];
    float4 x = ((float4*)buf)[i];
    x.x = (x.x >= 0.f) ? x.x : p * x.x;
    x.y = (x.y >= 0.f) ? x.y : p * x.y;
    x.z = (x.z >= 0.f) ? x.z : p * x.z;
    x.w = (x.w >= 0.f) ? x.w : p * x.w;
    ((float4*)buf)[i] = x;
}

// ---------------- 9) COO spmm scatter: dst[r] += val * src[c] --------------
__global__ void spmm_kernel(const int* __restrict__ idx, const float* __restrict__ vals,
                            int nnz, const float* __restrict__ src,
                            float* __restrict__ dst, float* __restrict__ tsum) {
    int gw = (blockIdx.x * blockDim.x + threadIdx.x) >> 5;
    int lane = threadIdx.x & 31;
    if (gw >= nnz) return;
    int r = idx[gw], c = idx[nnz + gw];
    float val = vals[gw];
    float2 x = *(const float2*)(src + (size_t)c * 64 + lane * 2);
    float2 v; v.x = val * x.x; v.y = val * x.y;
    atomicAdd((float2*)(dst + (size_t)r * 64 + lane * 2), v);
    if (tsum != nullptr && lane == 0) atomicAdd(&tsum[r], val);
}

// ---------------- 10) final: out = (H0 + S1 + V@triW + tsum*trib)/3 --------
__global__ void __launch_bounds__(256)
final_kernel(const float* __restrict__ triW, const float* __restrict__ trib,
             float* __restrict__ out, int n0) {
    __shared__ float sT[64 * 64];
    int t = threadIdx.x;
#pragma unroll
    for (int q = 0; q < 16; q++) sT[q * 256 + t] = triW[q * 256 + t];
    __syncthreads();
    int gw = blockIdx.x * 8 + (t >> 5);
    int lane = t & 31;
    if (gw >= n0) return;
    float2 v = *(const float2*)(g_V + (size_t)gw * 64 + lane * 2);
    float2 o; o.x = 0.f; o.y = 0.f;
#pragma unroll
    for (int k = 0; k < 64; k++) {
        float vk = __shfl_sync(0xffffffffu, (k & 1) ? v.y : v.x, k >> 1);
        float2 tw = *(const float2*)(sT + k * 64 + lane * 2);
        o.x = fmaf(vk, tw.x, o.x);
        o.y = fmaf(vk, tw.y, o.y);
    }
    float2 h0 = *(const float2*)(g_H0 + (size_t)gw * 64 + lane * 2);
    float2 s1 = *(const float2*)(g_S1 + (size_t)gw * 64 + lane * 2);
    float ts = g_tsum[gw];
    float2 tb = *(const float2*)(trib + lane * 2);
    float2 r;
    r.x = (h0.x + s1.x + o.x + ts * tb.x) * (1.f / 3.f);
    r.y = (h0.y + s1.y + o.y + ts * tb.y) * (1.f / 3.f);
    *(float2*)(out + (size_t)gw * 64 + lane * 2) = r;
}

// ======================== host launcher ====================================
static inline void* symaddr(const void* sym) {
    void* p = nullptr;
    cudaGetSymbolAddress(&p, sym);
    return p;
}

extern "C" void kernel_launch(void* const* d_in, const int* in_sizes, int n_in,
                              void* d_out, int out_size) {
    const float* X0  = (const float*)d_in[0];
    const int*   E1  = (const int*)d_in[1];
    const int*   T2  = (const int*)d_in[2];
    const int*   L0  = (const int*)d_in[3];
    const int*   L1a = (const int*)d_in[4];
    const int*   L1b = (const int*)d_in[5];
    const int*   L2  = (const int*)d_in[6];
    const int*   B1i = (const int*)d_in[7];
    const float* B1v = (const float*)d_in[8];
    const int*   B2i = (const int*)d_in[9];
    const float* B2v = (const float*)d_in[10];
    const float* W   = (const float*)d_in[11];
    const float* b   = (const float*)d_in[12];
    const float* a1w = (const float*)d_in[13];
    const float* a1b = (const float*)d_in[14];
    const float* a2w = (const float*)d_in[15];
    const float* a2b = (const float*)d_in[16];
    const float* pw  = (const float*)d_in[17];
    const float* triW = (const float*)d_in[18];
    const float* trib = (const float*)d_in[19];

    int n0 = in_sizes[0] / FINC;
    int n1 = in_sizes[1] / 2;
    int n2 = in_sizes[2] / 3;
    int nnz0  = in_sizes[3] / 2;
    int nnz1a = in_sizes[4] / 2;
    int nnz1b = in_sizes[5] / 2;
    int nnz2  = in_sizes[6] / 2;
    int nb1 = in_sizes[8];
    int nb2 = in_sizes[10];

    float* Xh0 = (float*)symaddr(g_Xh0);
    float* Xh1 = (float*)symaddr(g_Xh1);
    float* Xh2 = (float*)symaddr(g_Xh2);
    float* H0  = (float*)symaddr(g_H0);
    float* H1  = (float*)symaddr(g_H1);
    float* H2  = (float*)symaddr(g_H2);
    float* S1  = (float*)symaddr(g_S1);
    float* U   = (float*)symaddr(g_U);
    float* V   = (float*)symaddr(g_V);
    float* tsum = (float*)symaddr(g_tsum);
    void*  mx  = symaddr(g_mx);
    void*  z   = symaddr(g_z);

    static bool attr_set = false;
    if (!attr_set) {
        cudaFuncSetAttribute(mma_feat_kernel,
                             cudaFuncAttributeMaxDynamicSharedMemorySize, SMEM_TOTAL);
        attr_set = true;
    }

    // zero accumulators (graph-capturable memset nodes)
    cudaMemsetAsync(H0, 0, sizeof(float) * (size_t)n0 * 64);
    cudaMemsetAsync(H1, 0, sizeof(float) * (size_t)n1 * 64);
    cudaMemsetAsync(H2, 0, sizeof(float) * (size_t)n2 * 64);
    cudaMemsetAsync(S1, 0, sizeof(float) * (size_t)n0 * 64);
    cudaMemsetAsync(U,  0, sizeof(float) * (size_t)n1 * 64);
    cudaMemsetAsync(V,  0, sizeof(float) * (size_t)n0 * 64);
    cudaMemsetAsync(tsum, 0, sizeof(float) * (size_t)n0);
    cudaMemsetAsync(mx, 0, sizeof(unsigned) * 6 * N1C);   // 0 == encoded minimum
    cudaMemsetAsync(z,  0, sizeof(float) * 6 * N1C);

    // 1) pack bits, 2) pack weights (both formats)
    pack_bits_kernel<<<(n0 * 32 + 255) / 256, 256>>>(X0, n0);
    pack_Wt_kernel<<<(3 * 8 * 128 * 64 + 255) / 256, 256>>>(W, b);
    pack_W_kernel<<<(3 * 512 * 128 + 255) / 256, 256>>>(W);

    // 3) three feature GEMMs (two heads packed per level)
    mma_feat_kernel<<<(n0 + 127) / 128, 256, SMEM_TOTAL>>>(0, 0, n0, E1, Xh0);
    mma_feat_kernel<<<(n1 + 127) / 128, 256, SMEM_TOTAL>>>(1, 1, n1, E1, Xh1);
    mma_feat_kernel<<<(n2 + 127) / 128, 256, SMEM_TOTAL>>>(2, 2, n2, T2, Xh2);

    // 4) logits
    s_kernel<<<(n0 * 32 + 255) / 256, 256>>>(0, n0, Xh0, a1w, a1b, a2w, a2b);
    s_kernel<<<(n1 * 32 + 255) / 256, 256>>>(1, n1, Xh1, a1w, a1b, a2w, a2b);
    s_kernel<<<(n2 * 32 + 255) / 256, 256>>>(2, n2, Xh2, a1w, a1b, a2w, a2b);

    // 5) segment max
    att_max_kernel<<<(nnz0 + 255) / 256, 256>>>(L0, nnz0, 0, 1);
    att_max_kernel<<<(nnz1a + 255) / 256, 256>>>(L1a, nnz1a, 2, -1);
    att_max_kernel<<<(nnz1b + 255) / 256, 256>>>(L1b, nnz1b, 3, -1);
    att_max_kernel<<<(nnz2 + 255) / 256, 256>>>(L2, nnz2, 4, 5);

    // 6) exp + segment sum
    att_sumexp_kernel<<<(nnz0 + 255) / 256, 256>>>(L0, nnz0, 0, 1);
    att_sumexp_kernel<<<(nnz1a + 255) / 256, 256>>>(L1a, nnz1a, 2, -1);
    att_sumexp_kernel<<<(nnz1b + 255) / 256, 256>>>(L1b, nnz1b, 3, -1);
    att_sumexp_kernel<<<(nnz2 + 255) / 256, 256>>>(L2, nnz2, 4, 5);

    // 7) attention-weighted scatter (warp per nnz)
    att_scatter2_kernel<<<(nnz0 + 7) / 8, 256>>>(L0, nnz0, 0, 1, Xh0, H0);
    att_scatter1_kernel<<<(nnz1a + 7) / 8, 256>>>(L1a, nnz1a, 2, Xh1, H1);
    att_scatter1_kernel<<<(nnz1b + 7) / 8, 256>>>(L1b, nnz1b, 3, Xh1, H1);
    att_scatter2_kernel<<<(nnz2 + 7) / 8, 256>>>(L2, nnz2, 4, 5, Xh2, H2);

    // 8) PReLU
    prelu_kernel<<<((n0 * 64 / 4) + 255) / 256, 256>>>(H0, n0 * 16, pw);
    prelu_kernel<<<((n1 * 64 / 4) + 255) / 256, 256>>>(H1, n1 * 16, pw);
    prelu_kernel<<<((n2 * 64 / 4) + 255) / 256, 256>>>(H2, n2 * 16, pw);

    // 9) boundary spmms. spmm(B1, U@triW + trib) == spmm(B1,U)@triW + rowsum(B1)*trib
    spmm_kernel<<<(nb1 + 7) / 8, 256>>>(B1i, B1v, nb1, H1, S1, tsum);
    spmm_kernel<<<(nb2 + 7) / 8, 256>>>(B2i, B2v, nb2, H2, U, nullptr);
    spmm_kernel<<<(nb1 + 7) / 8, 256>>>(B1i, B1v, nb1, U, V, nullptr);

    // 10) combine
    final_kernel<<<(n0 + 7) / 8, 256>>>(triW, trib, (float*)d_out, n0);
}

// round 6
// speedup vs baseline: 2.7484x; 1.3905x over previous
#include <cuda_runtime.h>
#include <cuda_bf16.h>
#include <math.h>
#include <stdint.h>

// tcgen05 only exists in the arch-specific (sm_103a) device pass.
#if defined(__CUDA_ARCH_FEAT_SM103_ALL) || \
    (defined(__CUDA_ARCH_SPECIFIC__) && (__CUDA_ARCH__ == 1030))
#define HAS_TC 1
#else
#define HAS_TC 0
#endif

// ---------------- problem constants (fixed by the dataset) ----------------
#define N0C 50000
#define N1C 200000   // also max rows per level -> used as per-head stride
#define N2C 100000
#define FINC 500
#define DC 64

// ---------------- device scratch (no allocations allowed) ----------------
__device__ unsigned g_bits[N0C * 16];          // bit-packed binarized X0 (512 bits/node)
__device__ __align__(16) unsigned char g_Wt[3 * 2 * 8 * 16384]; // [lev][split][chunk] 128x64 bf16 SW128
__device__ float    g_Wp[3 * 512 * 128];       // fp32 packed weights (SIMT fallback)
__device__ float    g_bp[3 * 128];             // per-level packed bias
__device__ __align__(16) float g_Xh0[(size_t)N0C * 128];
__device__ __align__(16) float g_Xh1[(size_t)N1C * 128];
__device__ __align__(16) float g_Xh2[(size_t)N2C * 128];
__device__ float    g_p2[6 * N1C];             // exp(s2) per node per head
__device__ float    g_z [6 * N1C];             // softmax denominators
__device__ __align__(16) float g_Hu0[(size_t)N0C * 128]; // unnormalized dual-head accum
__device__ __align__(16) float g_Hu1[(size_t)N1C * 128];
__device__ __align__(16) float g_Hu2[(size_t)N2C * 128];
__device__ __align__(16) float g_H0[(size_t)N0C * 64];
__device__ __align__(16) float g_H1[(size_t)N1C * 64];
__device__ __align__(16) float g_H2[(size_t)N2C * 64];
__device__ __align__(16) float g_S1[(size_t)N0C * 64];   // spmm(B1, H1)
__device__ __align__(16) float g_U [(size_t)N1C * 64];   // spmm(B2, H2)
__device__ __align__(16) float g_V [(size_t)N0C * 64];   // spmm(B1, U)
__device__ float    g_tsum[N0C];               // rowsum of B1 values

// ---------------- PTX helpers (sm_103a-only emission) ----------------
__device__ __forceinline__ uint32_t smem_u32(const void* p) {
    uint32_t a;
    asm("{ .reg .u64 t; cvta.to.shared.u64 t, %1; cvt.u32.u64 %0, t; }" : "=r"(a) : "l"(p));
    return a;
}
#if HAS_TC
__device__ __forceinline__ uint32_t elect_one() {
    uint32_t pred;
    asm volatile("{\n\t.reg .pred p;\n\telect.sync _|p, 0xFFFFFFFF;\n\tselp.b32 %0, 1, 0, p;\n\t}" : "=r"(pred));
    return pred;
}
#define MBAR_INIT(addr, cnt) \
    asm volatile("mbarrier.init.shared.b64 [%0], %1;" :: "r"((uint32_t)(addr)), "r"((uint32_t)(cnt)) : "memory")
#define MBAR_WAIT(addr, par) do { \
    uint32_t _m = (uint32_t)(addr); uint32_t _p = (uint32_t)(par); uint32_t _d; \
    asm volatile("{\n\t.reg .pred p;\n\tmbarrier.try_wait.parity.acquire.cta.shared::cta.b64 p, [%1], %2;\n\tselp.b32 %0, 1, 0, p;\n\t}" \
        : "=r"(_d) : "r"(_m), "r"(_p) : "memory"); \
    if (!_d) { \
        asm volatile("{\n\t.reg .pred P1;\n\tWL_%=:\n\tmbarrier.try_wait.parity.acquire.cta.shared::cta.b64 P1, [%0], %1, 0x989680;\n\t@P1 bra.uni WD_%=;\n\tbra.uni WL_%=;\n\tWD_%=:\n\t}" \
            :: "r"(_m), "r"(_p) : "memory"); \
    } } while (0)
#define TC_ALLOC(sa, n)   asm volatile("tcgen05.alloc.cta_group::1.sync.aligned.shared::cta.b32 [%0], %1;" :: "r"((uint32_t)(sa)), "r"((uint32_t)(n)) : "memory")
#define TC_DEALLOC(t, n)  asm volatile("tcgen05.dealloc.cta_group::1.sync.aligned.b32 %0, %1;" :: "r"(t), "r"((uint32_t)(n)))
#define TC_COMMIT(mb)     asm volatile("tcgen05.commit.cta_group::1.mbarrier::arrive::one.shared::cluster.b64 [%0];" :: "r"((uint32_t)(mb)) : "memory")
#define TC_FENCE_AFTER()  asm volatile("tcgen05.fence::after_thread_sync;" ::: "memory")
#define TC_FENCE_BEFORE() asm volatile("tcgen05.fence::before_thread_sync;" ::: "memory")
#define TC_WAIT_LD()      asm volatile("tcgen05.wait::ld.sync.aligned;" ::: "memory")
#define FENCE_ASYNC()     asm volatile("fence.proxy.async.shared::cta;" ::: "memory")
#define TC_LD_X32(r, ta) \
    asm volatile("tcgen05.ld.sync.aligned.32x32b.x32.b32 " \
        "{%0, %1, %2, %3, %4, %5, %6, %7, %8, %9, %10, %11, %12, %13, %14, %15, " \
        " %16, %17, %18, %19, %20, %21, %22, %23, %24, %25, %26, %27, %28, %29, %30, %31}, [%32];" \
        : "=r"((r)[0]),  "=r"((r)[1]),  "=r"((r)[2]),  "=r"((r)[3]), \
          "=r"((r)[4]),  "=r"((r)[5]),  "=r"((r)[6]),  "=r"((r)[7]), \
          "=r"((r)[8]),  "=r"((r)[9]),  "=r"((r)[10]), "=r"((r)[11]), \
          "=r"((r)[12]), "=r"((r)[13]), "=r"((r)[14]), "=r"((r)[15]), \
          "=r"((r)[16]), "=r"((r)[17]), "=r"((r)[18]), "=r"((r)[19]), \
          "=r"((r)[20]), "=r"((r)[21]), "=r"((r)[22]), "=r"((r)[23]), \
          "=r"((r)[24]), "=r"((r)[25]), "=r"((r)[26]), "=r"((r)[27]), \
          "=r"((r)[28]), "=r"((r)[29]), "=r"((r)[30]), "=r"((r)[31]) \
        : "r"(ta))

static constexpr uint64_t DESC_BASE_SW128 =
    (uint64_t(2) << 61) | (uint64_t(1) << 46) | (uint64_t(64) << 32) | (uint64_t(1) << 16);
#define MAKE_DESC(a) (DESC_BASE_SW128 | ((uint64_t)((a) >> 4) & 0x3FFF))

// idesc: dtype F32, atype/btype BF16, N=64, M=128 (example-verified shape)
#define MMA_IDESC_N64 ((1u << 4) | (1u << 7) | (1u << 10) | ((64u / 8u) << 17) | ((128u / 16u) << 24))

__device__ __forceinline__ void mma_f16_ss(uint32_t d, uint64_t a, uint64_t b, bool en) {
    uint32_t e = en ? 1u : 0u;
    asm volatile(
        "{\n\t.reg .pred p;\n\tsetp.ne.u32 p, %5, 0;\n\t"
        "tcgen05.mma.cta_group::1.kind::f16 [%0], %1, %2, %3, {%4, %4, %4, %4}, p;\n\t}"
        :: "r"(d), "l"(a), "l"(b), "r"(MMA_IDESC_N64), "r"(0u), "r"(e)
        : "memory");
}
#endif  // HAS_TC

// ---------------- 1) binarize + bitpack X0 ----------------
__global__ void pack_bits_kernel(const float* __restrict__ X0, int n0) {
    int lane = threadIdx.x & 31;
    int node = (blockIdx.x * blockDim.x + threadIdx.x) >> 5;
    if (node >= n0) return;
    const float* row = X0 + (size_t)node * FINC;
#pragma unroll
    for (int wd = 0; wd < 16; wd++) {
        int bi = wd * 32 + lane;
        float f = (bi < FINC) ? row[bi] : 0.f;
        unsigned m = __ballot_sync(0xffffffffu, f != 0.f);
        if (lane == 0) g_bits[node * 16 + wd] = m;
    }
}

// ---------------- 2a) pack W into hi/lo bf16 SW128 tiles + bias -----------
__global__ void pack_Wt_kernel(const float* __restrict__ W, const float* __restrict__ b) {
    int idx = blockIdx.x * blockDim.x + threadIdx.x;
    if (idx >= 3 * 8 * 128 * 64) return;
    int kk = idx & 63;
    int n = (idx >> 6) & 127;
    int chunk = (idx >> 13) & 7;
    int lev = idx >> 16;
    int head = lev * 2 + (n >> 6);
    int jj = n & 63;
    int k = chunk * 64 + kk;
    float w = (k < FINC) ? W[((size_t)head * FINC + k) * DC + jj] : 0.f;
    __nv_bfloat16 hi = __float2bfloat16(w);
    __nv_bfloat16 lo = __float2bfloat16(w - __bfloat162float(hi));
    unsigned off = n * 128 + kk * 2;
    unsigned sw = off ^ ((off >> 3) & 0x70);
    size_t base_hi = (((size_t)lev * 2 + 0) * 8 + chunk) * 16384;
    size_t base_lo = (((size_t)lev * 2 + 1) * 8 + chunk) * 16384;
    *(__nv_bfloat16*)(g_Wt + base_hi + sw) = hi;
    *(__nv_bfloat16*)(g_Wt + base_lo + sw) = lo;
    if (k == 0) g_bp[lev * 128 + n] = b[head * DC + jj];
}

// ---------------- 2b) pack W fp32 [512 x 128] per level (fallback) --------
__global__ void pack_W_kernel(const float* __restrict__ W) {
    int idx = blockIdx.x * blockDim.x + threadIdx.x;
    if (idx >= 3 * 512 * 128) return;
    int lev = idx / (512 * 128);
    int rem = idx - lev * (512 * 128);
    int k = rem >> 7;
    int j = rem & 127;
    int head = lev * 2 + (j >> 6);
    int jj = j & 63;
    g_Wp[idx] = (k < FINC) ? W[((size_t)head * FINC + k) * DC + jj] : 0.f;
}

// ---------------- 3) feature GEMM: Xh[tile] = bits(A) @ W + bias ----------
// (unchanged from the round-5 PASSING configuration)
#define SM_A    0
#define SM_B    16384
#define SM_BITS 49152
#define SM_IDS  57344
#define SM_BIAS 58880
#define SM_LUT  59392
#define SM_PTR  59520
#define SM_MBAR 59528
#define SMEM_TOTAL (120 * 1024)
#define TMEM_COLS 512

__global__ void __launch_bounds__(256) __cluster_dims__(1, 1, 1)
mma_feat_kernel(int lev, int mode, int n, const int* __restrict__ elem,
                float* __restrict__ out) {
    extern __shared__ char smem[];
    int t = threadIdx.x;
    int tile0 = blockIdx.x * 128;

    if (t < 128) {
        int gr = tile0 + t; if (gr >= n) gr = n - 1;
        int a, bb, c;
        if (mode == 0)      { a = gr; bb = gr; c = gr; }
        else if (mode == 1) { a = elem[2 * gr]; bb = elem[2 * gr + 1]; c = a; }
        else                { a = elem[3 * gr]; bb = elem[3 * gr + 1]; c = elem[3 * gr + 2]; }
        int* ids = (int*)(smem + SM_IDS);
        ids[t * 3] = a; ids[t * 3 + 1] = bb; ids[t * 3 + 2] = c;
        ((float*)(smem + SM_BIAS))[t] = g_bp[lev * 128 + t];
    }
    __syncthreads();
    {
        const int* ids = (const int*)(smem + SM_IDS);
        unsigned* sbits = (unsigned*)(smem + SM_BITS);
        for (int i = t; i < 128 * 16; i += 256) {
            int row = i >> 4, w = i & 15;
            unsigned v = g_bits[ids[row * 3] * 16 + w];
            if (mode >= 1) v &= g_bits[ids[row * 3 + 1] * 16 + w];
            if (mode == 2) v &= g_bits[ids[row * 3 + 2] * 16 + w];
            sbits[i] = v;
        }
    }

#if HAS_TC
    uint32_t sb = smem_u32(smem);
    int wid = t >> 5;
    int lane = t & 31;
    if (wid == 0) {
        TC_ALLOC(sb + SM_PTR, TMEM_COLS);
    }
    if (t == 0) MBAR_INIT(sb + SM_MBAR, 1);
    if (t < 16) {
        unsigned w0 = ((t & 1) ? 0x3f80u : 0u) | ((t & 2) ? 0x3f800000u : 0u);
        unsigned w1 = ((t & 4) ? 0x3f80u : 0u) | ((t & 8) ? 0x3f800000u : 0u);
        ((uint2*)(smem + SM_LUT))[t] = make_uint2(w0, w1);
    }
    __syncthreads();

    uint32_t tmem;
    asm volatile("ld.shared.b32 %0, [%1];" : "=r"(tmem) : "r"(sb + SM_PTR));

    const uint2* lut = (const uint2*)(smem + SM_LUT);
    const unsigned* sbits = (const unsigned*)(smem + SM_BITS);
    int arow = t >> 1, ahalf = t & 1;
    const unsigned char* wt = g_Wt + (size_t)lev * (2 * 8 * 16384);

    for (int c = 0; c < 8; c++) {
        {
            unsigned bw = sbits[arow * 16 + 2 * c + ahalf];
            char* Abuf = smem + SM_A;
#pragma unroll
            for (int j = 0; j < 4; j++) {
                unsigned nib0 = (bw >> (j * 8)) & 15u;
                unsigned nib1 = (bw >> (j * 8 + 4)) & 15u;
                uint2 p0 = lut[nib0];
                uint2 p1 = lut[nib1];
                unsigned off = arow * 128 + ahalf * 64 + j * 16;
                unsigned sw = off ^ ((off >> 3) & 0x70);
                *(uint4*)(Abuf + sw) = make_uint4(p0.x, p0.y, p1.x, p1.y);
            }
        }
        {
            const uint4* srcHi = (const uint4*)(wt + (size_t)c * 16384);
            const uint4* srcLo = (const uint4*)(wt + (size_t)(8 + c) * 16384);
            uint4* dstB = (uint4*)(smem + SM_B);
#pragma unroll
            for (int q = 0; q < 4; q++) dstB[q * 256 + t] = srcHi[q * 256 + t];
#pragma unroll
            for (int q = 0; q < 4; q++) dstB[1024 + q * 256 + t] = srcLo[q * 256 + t];
        }
        FENCE_ASYNC();
        __syncthreads();

        if (wid == 0 && elect_one()) {
            uint64_t adesc  = MAKE_DESC(sb + SM_A);
            uint64_t bdescH = MAKE_DESC(sb + SM_B);
            uint64_t bdescL = MAKE_DESC(sb + SM_B + 16384);
#pragma unroll
            for (int ks = 0; ks < 4; ks++) {
                bool first = (c == 0 && ks == 0);
#pragma unroll
                for (int h = 0; h < 2; h++) {
                    mma_f16_ss(tmem + h * 64, adesc + ks * 2,
                               bdescH + h * 512 + ks * 2, !first);
                    mma_f16_ss(tmem + h * 64, adesc + ks * 2,
                               bdescL + h * 512 + ks * 2, true);
                }
            }
            TC_COMMIT(sb + SM_MBAR);
        }
        MBAR_WAIT(sb + SM_MBAR, c & 1);
        __syncthreads();
    }

    TC_FENCE_AFTER();

    {
        int part = wid & 3, colg = wid >> 2;
        uint32_t d0[32], d1[32];
        TC_LD_X32(d0, tmem + colg * 64);
        TC_LD_X32(d1, tmem + colg * 64 + 32);
        TC_WAIT_LD();
        TC_FENCE_BEFORE();
        int gr = tile0 + part * 32 + lane;
        if (gr < n) {
            const float* bias = (const float*)(smem + SM_BIAS) + colg * 64;
            float* o = out + (size_t)gr * 128 + colg * 64;
#pragma unroll
            for (int j = 0; j < 8; j++) {
                float4 v;
                v.x = __uint_as_float(d0[j * 4 + 0]) + bias[j * 4 + 0];
                v.y = __uint_as_float(d0[j * 4 + 1]) + bias[j * 4 + 1];
                v.z = __uint_as_float(d0[j * 4 + 2]) + bias[j * 4 + 2];
                v.w = __uint_as_float(d0[j * 4 + 3]) + bias[j * 4 + 3];
                *(float4*)(o + j * 4) = v;
            }
#pragma unroll
            for (int j = 0; j < 8; j++) {
                float4 v;
                v.x = __uint_as_float(d1[j * 4 + 0]) + bias[32 + j * 4 + 0];
                v.y = __uint_as_float(d1[j * 4 + 1]) + bias[32 + j * 4 + 1];
                v.z = __uint_as_float(d1[j * 4 + 2]) + bias[32 + j * 4 + 2];
                v.w = __uint_as_float(d1[j * 4 + 3]) + bias[32 + j * 4 + 3];
                *(float4*)(o + 32 + j * 4) = v;
            }
        }
    }
    __syncthreads();
    if (wid == 0) TC_DEALLOC(tmem, TMEM_COLS);

#else  // ---------------- SIMT fallback (non-sm_103a pass) ----------------
    const float* Wp = g_Wp + (size_t)lev * 512 * 128;
    float* sW = (float*)(smem + SM_A);
    const unsigned* sbits = (const unsigned*)(smem + SM_BITS);
    int tr = t >> 4, tc = t & 15;
    for (int h = 0; h < 2; h++) {
        float acc[4][8];
#pragma unroll
        for (int i = 0; i < 4; i++)
#pragma unroll
            for (int c = 0; c < 8; c++) acc[i][c] = 0.f;
        for (int w = 0; w < 16; w++) {
            __syncthreads();
            const float4* src = (const float4*)(Wp + (size_t)w * 4096);
            float4* dst = (float4*)sW;
#pragma unroll
            for (int q = 0; q < 4; q++) dst[q * 256 + t] = src[q * 256 + t];
            __syncthreads();
            unsigned a[4];
#pragma unroll
            for (int i = 0; i < 4; i++)
                a[i] = sbits[(h * 64 + tr + i * 16) * 16 + w];
            const float4* sv = (const float4*)sW;
#pragma unroll
            for (int kk = 0; kk < 32; kk++) {
                float4 w0 = sv[kk * 32 + tc * 2];
                float4 w1 = sv[kk * 32 + tc * 2 + 1];
#pragma unroll
                for (int i = 0; i < 4; i++) {
                    unsigned msk = (unsigned)(-(int)((a[i] >> kk) & 1u));
                    float av = __uint_as_float(0x3f800000u & msk);
                    acc[i][0] = fmaf(av, w0.x, acc[i][0]);
                    acc[i][1] = fmaf(av, w0.y, acc[i][1]);
                    acc[i][2] = fmaf(av, w0.z, acc[i][2]);
                    acc[i][3] = fmaf(av, w0.w, acc[i][3]);
                    acc[i][4] = fmaf(av, w1.x, acc[i][4]);
                    acc[i][5] = fmaf(av, w1.y, acc[i][5]);
                    acc[i][6] = fmaf(av, w1.z, acc[i][6]);
                    acc[i][7] = fmaf(av, w1.w, acc[i][7]);
                }
            }
        }
        const float* bias = (const float*)(smem + SM_BIAS) + tc * 8;
#pragma unroll
        for (int i = 0; i < 4; i++) {
            int r = tile0 + h * 64 + tr + i * 16;
            if (r < n) {
                float* o = out + (size_t)r * 128 + tc * 8;
#pragma unroll
                for (int c = 0; c < 8; c++) o[c] = acc[i][c] + bias[c];
            }
        }
    }
#endif
}

// ---------------- 4) p2 = exp(s2) per node, both heads --------------------
// s1 cancels in the row softmax (constant per row) -> never computed.
// No max subtraction: s2 ~ N(0, 0.63), exp() is safe in fp32.
__global__ void p2_kernel(int lev, int n, const float* __restrict__ Xh,
                          const float* __restrict__ a2w, const float* __restrict__ a2b) {
    int gw = (blockIdx.x * blockDim.x + threadIdx.x) >> 5;
    int lane = threadIdx.x & 31;
    if (gw >= n) return;
    float4 h = *(const float4*)(Xh + (size_t)gw * 128 + lane * 4);
    int head = 2 * lev + (lane >> 4);
    int off = head * 64 + (lane & 15) * 4;
    float4 w2 = *(const float4*)(a2w + off);
    float p2 = h.x * w2.x + h.y * w2.y + h.z * w2.z + h.w * w2.w;
#pragma unroll
    for (int o = 8; o >= 1; o >>= 1)
        p2 += __shfl_xor_sync(0xffffffffu, p2, o);
    if ((lane & 15) == 0)
        g_p2[head * N1C + gw] = expf(p2 + a2b[head]);
}

// ---------------- 5) fused dual-head attention scatter (shared idx) -------
// Hu layout interleaved: Hu[r*128 + l*4 + {0,1}] = head A cols {2l, 2l+1},
//                        Hu[r*128 + l*4 + {2,3}] = head B cols {2l, 2l+1}.
__global__ void att_scatter2_kernel(const int* __restrict__ idx, int nnz, int hA, int hB,
                                    const float* __restrict__ Xh, float* __restrict__ Hu) {
    int gw = (blockIdx.x * blockDim.x + threadIdx.x) >> 5;
    int lane = threadIdx.x & 31;
    if (gw >= nnz) return;
    int r = idx[gw], c = idx[nnz + gw];
    float eA = g_p2[hA * N1C + c];
    float eB = g_p2[hB * N1C + c];
    if (lane == 0)  atomicAdd(&g_z[hA * N1C + r], eA);
    if (lane == 16) atomicAdd(&g_z[hB * N1C + r], eB);
    float2 hAv = *(const float2*)(Xh + (size_t)c * 128 + lane * 2);
    float2 hBv = *(const float2*)(Xh + (size_t)c * 128 + 64 + lane * 2);
    float4 v;
    v.x = eA * hAv.x; v.y = eA * hAv.y;
    v.z = eB * hBv.x; v.w = eB * hBv.y;
    atomicAdd((float4*)(Hu + (size_t)r * 128 + lane * 4), v);
}

// ---------------- 6) single-head attention scatter (2 edges / warp) -------
// head h of level 1: reads Xh1 cols [hoff, hoff+64), accumulates into
// Hu1[r*128 + hoff .. +64).
__global__ void att_scatter1_kernel(const int* __restrict__ idx, int nnz, int head,
                                    const float* __restrict__ Xh, float* __restrict__ Hu) {
    int warp = (blockIdx.x * blockDim.x + threadIdx.x) >> 5;
    int lane = threadIdx.x & 31;
    int j = warp * 2 + (lane >> 4);
    int l = lane & 15;
    if (j >= nnz) return;
    int r = idx[j], c = idx[nnz + j];
    float e = g_p2[head * N1C + c];
    int hoff = (head & 1) * 64;
    if (l == 0) atomicAdd(&g_z[head * N1C + r], e);
    float4 hv = *(const float4*)(Xh + (size_t)c * 128 + hoff + l * 4);
    float4 v; v.x = e * hv.x; v.y = e * hv.y; v.z = e * hv.z; v.w = e * hv.w;
    atomicAdd((float4*)(Hu + (size_t)r * 128 + hoff + l * 4), v);
}

// ---------------- 7) normalize + sum heads + PReLU -------------------------
// interleaved=1: Hu layout from att_scatter2; interleaved=0: from att_scatter1.
__global__ void norm_prelu_kernel(int n, int hA, int hB, int interleaved,
                                  const float* __restrict__ Hu, float* __restrict__ H,
                                  const float* __restrict__ pw) {
    int gw = (blockIdx.x * blockDim.x + threadIdx.x) >> 5;
    int lane = threadIdx.x & 31;
    if (gw >= n) return;
    float za = g_z[hA * N1C + gw];
    float zb = g_z[hB * N1C + gw];
    float ia = (za > 0.f) ? 1.f / za : 0.f;
    float ib = (zb > 0.f) ? 1.f / zb : 0.f;
    float p = pw[0];
    float a0, a1, b0, b1;
    if (interleaved) {
        float4 q = *(const float4*)(Hu + (size_t)gw * 128 + lane * 4);
        a0 = q.x; a1 = q.y; b0 = q.z; b1 = q.w;
    } else {
        float2 qa = *(const float2*)(Hu + (size_t)gw * 128 + lane * 2);
        float2 qb = *(const float2*)(Hu + (size_t)gw * 128 + 64 + lane * 2);
        a0 = qa.x; a1 = qa.y; b0 = qb.x; b1 = qb.y;
    }
    float2 o;
    o.x = a0 * ia + b0 * ib;
    o.y = a1 * ia + b1 * ib;
    o.x = (o.x >= 0.f) ? o.x : p * o.x;
    o.y = (o.y >= 0.f) ? o.y : p * o.y;
    *(float2*)(H + (size_t)gw * 64 + lane * 2) = o;
}

// ---------------- 8) COO spmm: dst[r] += val*src[c] (2 nnz / warp) ---------
__global__ void spmm_kernel(const int* __restrict__ idx, const float* __restrict__ vals,
                            int nnz, const float* __restrict__ src, float* __restrict__ dst) {
    int warp = (blockIdx.x * blockDim.x + threadIdx.x) >> 5;
    int lane = threadIdx.x & 31;
    int j = warp * 2 + (lane >> 4);
    int l = lane & 15;
    if (j >= nnz) return;
    int r = idx[j], c = idx[nnz + j];
    float val = vals[j];
    float4 x = *(const float4*)(src + (size_t)c * 64 + l * 4);
    float4 v; v.x = val * x.x; v.y = val * x.y; v.z = val * x.z; v.w = val * x.w;
    atomicAdd((float4*)(dst + (size_t)r * 64 + l * 4), v);
}

// ---------------- 9) fused B1 spmm: S1 += val*H1[c]; V += val*U[c]; tsum ---
__global__ void spmm_b1_fused_kernel(const int* __restrict__ idx, const float* __restrict__ vals,
                                     int nnz) {
    int warp = (blockIdx.x * blockDim.x + threadIdx.x) >> 5;
    int lane = threadIdx.x & 31;
    int j = warp * 2 + (lane >> 4);
    int l = lane & 15;
    if (j >= nnz) return;
    int r = idx[j], c = idx[nnz + j];
    float val = vals[j];
    if (l == 0) atomicAdd(&g_tsum[r], val);
    float4 x1 = *(const float4*)(g_H1 + (size_t)c * 64 + l * 4);
    float4 xu = *(const float4*)(g_U  + (size_t)c * 64 + l * 4);
    float4 v1; v1.x = val * x1.x; v1.y = val * x1.y; v1.z = val * x1.z; v1.w = val * x1.w;
    float4 vu; vu.x = val * xu.x; vu.y = val * xu.y; vu.z = val * xu.z; vu.w = val * xu.w;
    atomicAdd((float4*)(g_S1 + (size_t)r * 64 + l * 4), v1);
    atomicAdd((float4*)(g_V  + (size_t)r * 64 + l * 4), vu);
}

// ---------------- 10) final: out = (H0 + S1 + V@triW + tsum*trib)/3 --------
__global__ void __launch_bounds__(256)
final_kernel(const float* __restrict__ triW, const float* __restrict__ trib,
             float* __restrict__ out, int n0) {
    __shared__ float sT[64 * 64];
    int t = threadIdx.x;
#pragma unroll
    for (int q = 0; q < 16; q++) sT[q * 256 + t] = triW[q * 256 + t];
    __syncthreads();
    int gw = blockIdx.x * 8 + (t >> 5);
    int lane = t & 31;
    if (gw >= n0) return;
    float2 v = *(const float2*)(g_V + (size_t)gw * 64 + lane * 2);
    float2 o; o.x = 0.f; o.y = 0.f;
#pragma unroll
    for (int k = 0; k < 64; k++) {
        float vk = __shfl_sync(0xffffffffu, (k & 1) ? v.y : v.x, k >> 1);
        float2 tw = *(const float2*)(sT + k * 64 + lane * 2);
        o.x = fmaf(vk, tw.x, o.x);
        o.y = fmaf(vk, tw.y, o.y);
    }
    float2 h0 = *(const float2*)(g_H0 + (size_t)gw * 64 + lane * 2);
    float2 s1 = *(const float2*)(g_S1 + (size_t)gw * 64 + lane * 2);
    float ts = g_tsum[gw];
    float2 tb = *(const float2*)(trib + lane * 2);
    float2 r;
    r.x = (h0.x + s1.x + o.x + ts * tb.x) * (1.f / 3.f);
    r.y = (h0.y + s1.y + o.y + ts * tb.y) * (1.f / 3.f);
    *(float2*)(out + (size_t)gw * 64 + lane * 2) = r;
}

// ======================== host launcher ====================================
static inline void* symaddr(const void* sym) {
    void* p = nullptr;
    cudaGetSymbolAddress(&p, sym);
    return p;
}

extern "C" void kernel_launch(void* const* d_in, const int* in_sizes, int n_in,
                              void* d_out, int out_size) {
    const float* X0  = (const float*)d_in[0];
    const int*   E1  = (const int*)d_in[1];
    const int*   T2  = (const int*)d_in[2];
    const int*   L0  = (const int*)d_in[3];
    const int*   L1a = (const int*)d_in[4];
    const int*   L1b = (const int*)d_in[5];
    const int*   L2  = (const int*)d_in[6];
    const int*   B1i = (const int*)d_in[7];
    const float* B1v = (const float*)d_in[8];
    const int*   B2i = (const int*)d_in[9];
    const float* B2v = (const float*)d_in[10];
    const float* W   = (const float*)d_in[11];
    const float* b   = (const float*)d_in[12];
    const float* a2w = (const float*)d_in[15];
    const float* a2b = (const float*)d_in[16];
    const float* pw  = (const float*)d_in[17];
    const float* triW = (const float*)d_in[18];
    const float* trib = (const float*)d_in[19];

    int n0 = in_sizes[0] / FINC;
    int n1 = in_sizes[1] / 2;
    int n2 = in_sizes[2] / 3;
    int nnz0  = in_sizes[3] / 2;
    int nnz1a = in_sizes[4] / 2;
    int nnz1b = in_sizes[5] / 2;
    int nnz2  = in_sizes[6] / 2;
    int nb1 = in_sizes[8];
    int nb2 = in_sizes[10];

    float* Xh0 = (float*)symaddr(g_Xh0);
    float* Xh1 = (float*)symaddr(g_Xh1);
    float* Xh2 = (float*)symaddr(g_Xh2);
    float* Hu0 = (float*)symaddr(g_Hu0);
    float* Hu1 = (float*)symaddr(g_Hu1);
    float* Hu2 = (float*)symaddr(g_Hu2);
    float* H0  = (float*)symaddr(g_H0);
    float* H1  = (float*)symaddr(g_H1);
    float* H2  = (float*)symaddr(g_H2);
    float* S1  = (float*)symaddr(g_S1);
    float* U   = (float*)symaddr(g_U);
    float* V   = (float*)symaddr(g_V);
    float* tsum = (float*)symaddr(g_tsum);
    void*  z   = symaddr(g_z);

    static bool attr_set = false;
    if (!attr_set) {
        cudaFuncSetAttribute(mma_feat_kernel,
                             cudaFuncAttributeMaxDynamicSharedMemorySize, SMEM_TOTAL);
        attr_set = true;
    }

    // zero accumulators (graph-capturable memset nodes)
    cudaMemsetAsync(Hu0, 0, sizeof(float) * (size_t)n0 * 128);
    cudaMemsetAsync(Hu1, 0, sizeof(float) * (size_t)n1 * 128);
    cudaMemsetAsync(Hu2, 0, sizeof(float) * (size_t)n2 * 128);
    cudaMemsetAsync(S1, 0, sizeof(float) * (size_t)n0 * 64);
    cudaMemsetAsync(U,  0, sizeof(float) * (size_t)n1 * 64);
    cudaMemsetAsync(V,  0, sizeof(float) * (size_t)n0 * 64);
    cudaMemsetAsync(tsum, 0, sizeof(float) * (size_t)n0);
    cudaMemsetAsync(z,  0, sizeof(float) * 6 * N1C);

    // 1) pack bits, 2) pack weights (both formats)
    pack_bits_kernel<<<(n0 * 32 + 255) / 256, 256>>>(X0, n0);
    pack_Wt_kernel<<<(3 * 8 * 128 * 64 + 255) / 256, 256>>>(W, b);
    pack_W_kernel<<<(3 * 512 * 128 + 255) / 256, 256>>>(W);

    // 3) three feature GEMMs (two heads packed per level)
    mma_feat_kernel<<<(n0 + 127) / 128, 256, SMEM_TOTAL>>>(0, 0, n0, E1, Xh0);
    mma_feat_kernel<<<(n1 + 127) / 128, 256, SMEM_TOTAL>>>(1, 1, n1, E1, Xh1);
    mma_feat_kernel<<<(n2 + 127) / 128, 256, SMEM_TOTAL>>>(2, 2, n2, T2, Xh2);

    // 4) per-node exp(s2) (s1 cancels in the row softmax)
    p2_kernel<<<(n0 * 32 + 255) / 256, 256>>>(0, n0, Xh0, a2w, a2b);
    p2_kernel<<<(n1 * 32 + 255) / 256, 256>>>(1, n1, Xh1, a2w, a2b);
    p2_kernel<<<(n2 * 32 + 255) / 256, 256>>>(2, n2, Xh2, a2w, a2b);

    // 5) single-pass unnormalized attention scatter + z accumulation
    att_scatter2_kernel<<<(nnz0 + 7) / 8, 256>>>(L0, nnz0, 0, 1, Xh0, Hu0);
    att_scatter1_kernel<<<(nnz1a + 15) / 16, 256>>>(L1a, nnz1a, 2, Xh1, Hu1);
    att_scatter1_kernel<<<(nnz1b + 15) / 16, 256>>>(L1b, nnz1b, 3, Xh1, Hu1);
    att_scatter2_kernel<<<(nnz2 + 7) / 8, 256>>>(L2, nnz2, 4, 5, Xh2, Hu2);

    // 6) normalize + sum heads + PReLU
    norm_prelu_kernel<<<(n0 + 7) / 8, 256>>>(n0, 0, 1, 1, Hu0, H0, pw);
    norm_prelu_kernel<<<(n1 + 7) / 8, 256>>>(n1, 2, 3, 0, Hu1, H1, pw);
    norm_prelu_kernel<<<(n2 + 7) / 8, 256>>>(n2, 4, 5, 1, Hu2, H2, pw);

    // 7) boundary spmms. spmm(B1, U@triW + trib) == spmm(B1,U)@triW + rowsum(B1)*trib
    spmm_kernel<<<(nb2 + 15) / 16, 256>>>(B2i, B2v, nb2, H2, U);
    spmm_b1_fused_kernel<<<(nb1 + 15) / 16, 256>>>(B1i, B1v, nb1);

    // 8) combine
    final_kernel<<<(n0 + 7) / 8, 256>>>(triW, trib, (float*)d_out, n0);
}

// round 7
// speedup vs baseline: 3.4016x; 1.2377x over previous
#include <cuda_runtime.h>
#include <cuda_bf16.h>
#include <math.h>
#include <stdint.h>

// tcgen05 only exists in the arch-specific (sm_103a) device pass.
#if defined(__CUDA_ARCH_FEAT_SM103_ALL) || \
    (defined(__CUDA_ARCH_SPECIFIC__) && (__CUDA_ARCH__ == 1030))
#define HAS_TC 1
#else
#define HAS_TC 0
#endif

// ---------------- problem constants (fixed by the dataset) ----------------
#define N0C 50000
#define N1C 200000   // also max rows per level -> used as per-head stride
#define N2C 100000
#define FINC 500
#define DC 64

// ---------------- device scratch (no allocations allowed) ----------------
__device__ unsigned g_bits[N0C * 16];          // bit-packed binarized X0 (512 bits/node)
__device__ __align__(16) unsigned char g_Wt[3 * 2 * 8 * 16384]; // [lev][split][chunk] 128x64 bf16 SW128
__device__ float    g_Wp[3 * 512 * 128];       // fp32 packed weights (SIMT fallback)
__device__ float    g_bp[3 * 128];             // per-level packed bias
__device__ __align__(16) float g_Xh0[(size_t)N0C * 128];
__device__ __align__(16) float g_Xh1[(size_t)N1C * 128];
__device__ __align__(16) float g_Xh2[(size_t)N2C * 128];
__device__ float    g_p2[6 * N1C];             // exp(s2) per node per head
__device__ float    g_z [6 * N1C];             // softmax denominators
__device__ __align__(16) float g_H0[(size_t)N0C * 64];
__device__ __align__(16) float g_H1[(size_t)N1C * 64];
__device__ __align__(16) float g_H2[(size_t)N2C * 64];
__device__ __align__(16) float g_S1[(size_t)N0C * 64];   // spmm(B1, prelu(H1))
__device__ __align__(16) float g_U [(size_t)N1C * 64];   // spmm(B2, prelu(H2))
__device__ __align__(16) float g_V [(size_t)N0C * 64];   // spmm(B1, U)
__device__ float    g_tsum[N0C];               // rowsum of B1 values

// ---------------- PTX helpers (sm_103a-only emission) ----------------
__device__ __forceinline__ uint32_t smem_u32(const void* p) {
    uint32_t a;
    asm("{ .reg .u64 t; cvta.to.shared.u64 t, %1; cvt.u32.u64 %0, t; }" : "=r"(a) : "l"(p));
    return a;
}
#if HAS_TC
__device__ __forceinline__ uint32_t elect_one() {
    uint32_t pred;
    asm volatile("{\n\t.reg .pred p;\n\telect.sync _|p, 0xFFFFFFFF;\n\tselp.b32 %0, 1, 0, p;\n\t}" : "=r"(pred));
    return pred;
}
#define MBAR_INIT(addr, cnt) \
    asm volatile("mbarrier.init.shared.b64 [%0], %1;" :: "r"((uint32_t)(addr)), "r"((uint32_t)(cnt)) : "memory")
#define MBAR_WAIT(addr, par) do { \
    uint32_t _m = (uint32_t)(addr); uint32_t _p = (uint32_t)(par); uint32_t _d; \
    asm volatile("{\n\t.reg .pred p;\n\tmbarrier.try_wait.parity.acquire.cta.shared::cta.b64 p, [%1], %2;\n\tselp.b32 %0, 1, 0, p;\n\t}" \
        : "=r"(_d) : "r"(_m), "r"(_p) : "memory"); \
    if (!_d) { \
        asm volatile("{\n\t.reg .pred P1;\n\tWL_%=:\n\tmbarrier.try_wait.parity.acquire.cta.shared::cta.b64 P1, [%0], %1, 0x989680;\n\t@P1 bra.uni WD_%=;\n\tbra.uni WL_%=;\n\tWD_%=:\n\t}" \
            :: "r"(_m), "r"(_p) : "memory"); \
    } } while (0)
#define TC_ALLOC(sa, n)   asm volatile("tcgen05.alloc.cta_group::1.sync.aligned.shared::cta.b32 [%0], %1;" :: "r"((uint32_t)(sa)), "r"((uint32_t)(n)) : "memory")
#define TC_DEALLOC(t, n)  asm volatile("tcgen05.dealloc.cta_group::1.sync.aligned.b32 %0, %1;" :: "r"(t), "r"((uint32_t)(n)))
#define TC_COMMIT(mb)     asm volatile("tcgen05.commit.cta_group::1.mbarrier::arrive::one.shared::cluster.b64 [%0];" :: "r"((uint32_t)(mb)) : "memory")
#define TC_FENCE_AFTER()  asm volatile("tcgen05.fence::after_thread_sync;" ::: "memory")
#define TC_FENCE_BEFORE() asm volatile("tcgen05.fence::before_thread_sync;" ::: "memory")
#define TC_WAIT_LD()      asm volatile("tcgen05.wait::ld.sync.aligned;" ::: "memory")
#define FENCE_ASYNC()     asm volatile("fence.proxy.async.shared::cta;" ::: "memory")
#define TC_LD_X32(r, ta) \
    asm volatile("tcgen05.ld.sync.aligned.32x32b.x32.b32 " \
        "{%0, %1, %2, %3, %4, %5, %6, %7, %8, %9, %10, %11, %12, %13, %14, %15, " \
        " %16, %17, %18, %19, %20, %21, %22, %23, %24, %25, %26, %27, %28, %29, %30, %31}, [%32];" \
        : "=r"((r)[0]),  "=r"((r)[1]),  "=r"((r)[2]),  "=r"((r)[3]), \
          "=r"((r)[4]),  "=r"((r)[5]),  "=r"((r)[6]),  "=r"((r)[7]), \
          "=r"((r)[8]),  "=r"((r)[9]),  "=r"((r)[10]), "=r"((r)[11]), \
          "=r"((r)[12]), "=r"((r)[13]), "=r"((r)[14]), "=r"((r)[15]), \
          "=r"((r)[16]), "=r"((r)[17]), "=r"((r)[18]), "=r"((r)[19]), \
          "=r"((r)[20]), "=r"((r)[21]), "=r"((r)[22]), "=r"((r)[23]), \
          "=r"((r)[24]), "=r"((r)[25]), "=r"((r)[26]), "=r"((r)[27]), \
          "=r"((r)[28]), "=r"((r)[29]), "=r"((r)[30]), "=r"((r)[31]) \
        : "r"(ta))

static constexpr uint64_t DESC_BASE_SW128 =
    (uint64_t(2) << 61) | (uint64_t(1) << 46) | (uint64_t(64) << 32) | (uint64_t(1) << 16);
#define MAKE_DESC(a) (DESC_BASE_SW128 | ((uint64_t)((a) >> 4) & 0x3FFF))

// idesc: dtype F32, atype/btype BF16, N=64, M=128 (example-verified shape)
#define MMA_IDESC_N64 ((1u << 4) | (1u << 7) | (1u << 10) | ((64u / 8u) << 17) | ((128u / 16u) << 24))

__device__ __forceinline__ void mma_f16_ss(uint32_t d, uint64_t a, uint64_t b, bool en) {
    uint32_t e = en ? 1u : 0u;
    asm volatile(
        "{\n\t.reg .pred p;\n\tsetp.ne.u32 p, %5, 0;\n\t"
        "tcgen05.mma.cta_group::1.kind::f16 [%0], %1, %2, %3, {%4, %4, %4, %4}, p;\n\t}"
        :: "r"(d), "l"(a), "l"(b), "r"(MMA_IDESC_N64), "r"(0u), "r"(e)
        : "memory");
}
#endif  // HAS_TC

// ---------------- 1) binarize + bitpack X0 ----------------
__global__ void pack_bits_kernel(const float* __restrict__ X0, int n0) {
    int lane = threadIdx.x & 31;
    int node = (blockIdx.x * blockDim.x + threadIdx.x) >> 5;
    if (node >= n0) return;
    const float* row = X0 + (size_t)node * FINC;
#pragma unroll
    for (int wd = 0; wd < 16; wd++) {
        int bi = wd * 32 + lane;
        float f = (bi < FINC) ? row[bi] : 0.f;
        unsigned m = __ballot_sync(0xffffffffu, f != 0.f);
        if (lane == 0) g_bits[node * 16 + wd] = m;
    }
}

// ---------------- 2a) pack W into hi/lo bf16 SW128 tiles + bias -----------
__global__ void pack_Wt_kernel(const float* __restrict__ W, const float* __restrict__ b) {
    int idx = blockIdx.x * blockDim.x + threadIdx.x;
    if (idx >= 3 * 8 * 128 * 64) return;
    int kk = idx & 63;
    int n = (idx >> 6) & 127;
    int chunk = (idx >> 13) & 7;
    int lev = idx >> 16;
    int head = lev * 2 + (n >> 6);
    int jj = n & 63;
    int k = chunk * 64 + kk;
    float w = (k < FINC) ? W[((size_t)head * FINC + k) * DC + jj] : 0.f;
    __nv_bfloat16 hi = __float2bfloat16(w);
    __nv_bfloat16 lo = __float2bfloat16(w - __bfloat162float(hi));
    unsigned off = n * 128 + kk * 2;
    unsigned sw = off ^ ((off >> 3) & 0x70);
    size_t base_hi = (((size_t)lev * 2 + 0) * 8 + chunk) * 16384;
    size_t base_lo = (((size_t)lev * 2 + 1) * 8 + chunk) * 16384;
    *(__nv_bfloat16*)(g_Wt + base_hi + sw) = hi;
    *(__nv_bfloat16*)(g_Wt + base_lo + sw) = lo;
    if (k == 0) g_bp[lev * 128 + n] = b[head * DC + jj];
}

// ---------------- 2b) pack W fp32 [512 x 128] per level (fallback) --------
__global__ void pack_W_kernel(const float* __restrict__ W) {
    int idx = blockIdx.x * blockDim.x + threadIdx.x;
    if (idx >= 3 * 512 * 128) return;
    int lev = idx / (512 * 128);
    int rem = idx - lev * (512 * 128);
    int k = rem >> 7;
    int j = rem & 127;
    int head = lev * 2 + (j >> 6);
    int jj = j & 63;
    g_Wp[idx] = (k < FINC) ? W[((size_t)head * FINC + k) * DC + jj] : 0.f;
}

// ---------------- 3) feature GEMM + fused p2 epilogue ----------------------
// SMEM layout: double-buffered A/B pipeline (alloc config from passing R5)
#define SM_A    0        // 2 x 16384
#define SM_B    32768    // 2 x 32768 (each: hi 16K + lo 16K)
#define SM_BITS 98304    // 8192
#define SM_IDS  106496   // 1536
#define SM_BIAS 108032   // 512
#define SM_A2W  108544   // 512 (128 floats: a2w for both heads of level)
#define SM_A2B  109056   // 8
#define SM_LUT  109072   // 128
#define SM_PTR  109200   // 8
#define SM_MBAR 109208   // 16 (2 mbarriers)
#define SMEM_TOTAL (120 * 1024)
#define TMEM_COLS 512

__global__ void __launch_bounds__(256) __cluster_dims__(1, 1, 1)
mma_feat_kernel(int lev, int mode, int n, const int* __restrict__ elem,
                float* __restrict__ out,
                const float* __restrict__ a2w, const float* __restrict__ a2b) {
    extern __shared__ char smem[];
    int t = threadIdx.x;
    int tile0 = blockIdx.x * 128;

    if (t < 128) {
        int gr = tile0 + t; if (gr >= n) gr = n - 1;
        int a, bb, c;
        if (mode == 0)      { a = gr; bb = gr; c = gr; }
        else if (mode == 1) { a = elem[2 * gr]; bb = elem[2 * gr + 1]; c = a; }
        else                { a = elem[3 * gr]; bb = elem[3 * gr + 1]; c = elem[3 * gr + 2]; }
        int* ids = (int*)(smem + SM_IDS);
        ids[t * 3] = a; ids[t * 3 + 1] = bb; ids[t * 3 + 2] = c;
        ((float*)(smem + SM_BIAS))[t] = g_bp[lev * 128 + t];
        ((float*)(smem + SM_A2W))[t] = a2w[(lev * 2 + (t >> 6)) * 64 + (t & 63)];
    }
    if (t < 2) ((float*)(smem + SM_A2B))[t] = a2b[lev * 2 + t];
    __syncthreads();
    {
        const int* ids = (const int*)(smem + SM_IDS);
        unsigned* sbits = (unsigned*)(smem + SM_BITS);
        for (int i = t; i < 128 * 16; i += 256) {
            int row = i >> 4, w = i & 15;
            unsigned v = g_bits[ids[row * 3] * 16 + w];
            if (mode >= 1) v &= g_bits[ids[row * 3 + 1] * 16 + w];
            if (mode == 2) v &= g_bits[ids[row * 3 + 2] * 16 + w];
            sbits[i] = v;
        }
    }

#if HAS_TC
    uint32_t sb = smem_u32(smem);
    int wid = t >> 5;
    int lane = t & 31;
    if (wid == 0) {
        TC_ALLOC(sb + SM_PTR, TMEM_COLS);
    }
    if (t == 0) { MBAR_INIT(sb + SM_MBAR, 1); MBAR_INIT(sb + SM_MBAR + 8, 1); }
    if (t < 16) {
        unsigned w0 = ((t & 1) ? 0x3f80u : 0u) | ((t & 2) ? 0x3f800000u : 0u);
        unsigned w1 = ((t & 4) ? 0x3f80u : 0u) | ((t & 8) ? 0x3f800000u : 0u);
        ((uint2*)(smem + SM_LUT))[t] = make_uint2(w0, w1);
    }
    __syncthreads();

    uint32_t tmem;
    asm volatile("ld.shared.b32 %0, [%1];" : "=r"(tmem) : "r"(sb + SM_PTR));

    const uint2* lut = (const uint2*)(smem + SM_LUT);
    const unsigned* sbits = (const unsigned*)(smem + SM_BITS);
    int arow = t >> 1, ahalf = t & 1;
    const unsigned char* wt = g_Wt + (size_t)lev * (2 * 8 * 16384);

    // double-buffered pipeline: write buf (c&1), commit MMA, wait only on reuse
    for (int c = 0; c < 8; c++) {
        int buf = c & 1;
        if (c >= 2) {
            MBAR_WAIT(sb + SM_MBAR + buf * 8, ((c - 2 - buf) >> 1) & 1);
        }
        {
            unsigned bw = sbits[arow * 16 + 2 * c + ahalf];
            char* Abuf = smem + SM_A + buf * 16384;
#pragma unroll
            for (int j = 0; j < 4; j++) {
                unsigned nib0 = (bw >> (j * 8)) & 15u;
                unsigned nib1 = (bw >> (j * 8 + 4)) & 15u;
                uint2 p0 = lut[nib0];
                uint2 p1 = lut[nib1];
                unsigned off = arow * 128 + ahalf * 64 + j * 16;
                unsigned sw = off ^ ((off >> 3) & 0x70);
                *(uint4*)(Abuf + sw) = make_uint4(p0.x, p0.y, p1.x, p1.y);
            }
        }
        {
            const uint4* srcHi = (const uint4*)(wt + (size_t)c * 16384);
            const uint4* srcLo = (const uint4*)(wt + (size_t)(8 + c) * 16384);
            uint4* dstB = (uint4*)(smem + SM_B + buf * 32768);
#pragma unroll
            for (int q = 0; q < 4; q++) dstB[q * 256 + t] = srcHi[q * 256 + t];
#pragma unroll
            for (int q = 0; q < 4; q++) dstB[1024 + q * 256 + t] = srcLo[q * 256 + t];
        }
        FENCE_ASYNC();
        __syncthreads();

        if (wid == 0 && elect_one()) {
            uint64_t adesc  = MAKE_DESC(sb + SM_A + buf * 16384);
            uint64_t bdescH = MAKE_DESC(sb + SM_B + buf * 32768);
            uint64_t bdescL = MAKE_DESC(sb + SM_B + buf * 32768 + 16384);
#pragma unroll
            for (int ks = 0; ks < 4; ks++) {
                bool first = (c == 0 && ks == 0);
#pragma unroll
                for (int h = 0; h < 2; h++) {
                    mma_f16_ss(tmem + h * 64, adesc + ks * 2,
                               bdescH + h * 512 + ks * 2, !first);
                    mma_f16_ss(tmem + h * 64, adesc + ks * 2,
                               bdescL + h * 512 + ks * 2, true);
                }
            }
            TC_COMMIT(sb + SM_MBAR + buf * 8);
        }
    }

    // final commits per mbar: 4 completions -> last phase parity 1
    MBAR_WAIT(sb + SM_MBAR, 1);
    MBAR_WAIT(sb + SM_MBAR + 8, 1);
    TC_FENCE_AFTER();

    // epilogue: warp -> (subpartition = wid&3 rows, colgroup/head = wid>>2)
    {
        int part = wid & 3, colg = wid >> 2;
        uint32_t d0[32], d1[32];
        TC_LD_X32(d0, tmem + colg * 64);
        TC_LD_X32(d1, tmem + colg * 64 + 32);
        TC_WAIT_LD();
        TC_FENCE_BEFORE();
        int gr = tile0 + part * 32 + lane;
        if (gr < n) {
            const float* bias = (const float*)(smem + SM_BIAS) + colg * 64;
            const float* sa2w = (const float*)(smem + SM_A2W) + colg * 64;
            float* o = out + (size_t)gr * 128 + colg * 64;
            float s2 = 0.f;
#pragma unroll
            for (int j = 0; j < 8; j++) {
                float4 v;
                v.x = __uint_as_float(d0[j * 4 + 0]) + bias[j * 4 + 0];
                v.y = __uint_as_float(d0[j * 4 + 1]) + bias[j * 4 + 1];
                v.z = __uint_as_float(d0[j * 4 + 2]) + bias[j * 4 + 2];
                v.w = __uint_as_float(d0[j * 4 + 3]) + bias[j * 4 + 3];
                s2 = fmaf(v.x, sa2w[j * 4 + 0], s2);
                s2 = fmaf(v.y, sa2w[j * 4 + 1], s2);
                s2 = fmaf(v.z, sa2w[j * 4 + 2], s2);
                s2 = fmaf(v.w, sa2w[j * 4 + 3], s2);
                *(float4*)(o + j * 4) = v;
            }
#pragma unroll
            for (int j = 0; j < 8; j++) {
                float4 v;
                v.x = __uint_as_float(d1[j * 4 + 0]) + bias[32 + j * 4 + 0];
                v.y = __uint_as_float(d1[j * 4 + 1]) + bias[32 + j * 4 + 1];
                v.z = __uint_as_float(d1[j * 4 + 2]) + bias[32 + j * 4 + 2];
                v.w = __uint_as_float(d1[j * 4 + 3]) + bias[32 + j * 4 + 3];
                s2 = fmaf(v.x, sa2w[32 + j * 4 + 0], s2);
                s2 = fmaf(v.y, sa2w[32 + j * 4 + 1], s2);
                s2 = fmaf(v.z, sa2w[32 + j * 4 + 2], s2);
                s2 = fmaf(v.w, sa2w[32 + j * 4 + 3], s2);
                *(float4*)(o + 32 + j * 4) = v;
            }
            float a2bv = ((const float*)(smem + SM_A2B))[colg];
            g_p2[(lev * 2 + colg) * N1C + gr] = expf(s2 + a2bv);
        }
    }
    __syncthreads();
    if (wid == 0) TC_DEALLOC(tmem, TMEM_COLS);

#else  // ---------------- SIMT fallback (non-sm_103a pass; dead on GB300) --
    const float* Wp = g_Wp + (size_t)lev * 512 * 128;
    float* sW = (float*)(smem + SM_A);
    const unsigned* sbits = (const unsigned*)(smem + SM_BITS);
    int tr = t >> 4, tc = t & 15;
    for (int h = 0; h < 2; h++) {
        float acc[4][8];
#pragma unroll
        for (int i = 0; i < 4; i++)
#pragma unroll
            for (int c = 0; c < 8; c++) acc[i][c] = 0.f;
        for (int w = 0; w < 16; w++) {
            __syncthreads();
            const float4* src = (const float4*)(Wp + (size_t)w * 4096);
            float4* dst = (float4*)sW;
#pragma unroll
            for (int q = 0; q < 4; q++) dst[q * 256 + t] = src[q * 256 + t];
            __syncthreads();
            unsigned a[4];
#pragma unroll
            for (int i = 0; i < 4; i++)
                a[i] = sbits[(h * 64 + tr + i * 16) * 16 + w];
            const float4* sv = (const float4*)sW;
#pragma unroll
            for (int kk = 0; kk < 32; kk++) {
                float4 w0 = sv[kk * 32 + tc * 2];
                float4 w1 = sv[kk * 32 + tc * 2 + 1];
#pragma unroll
                for (int i = 0; i < 4; i++) {
                    unsigned msk = (unsigned)(-(int)((a[i] >> kk) & 1u));
                    float av = __uint_as_float(0x3f800000u & msk);
                    acc[i][0] = fmaf(av, w0.x, acc[i][0]);
                    acc[i][1] = fmaf(av, w0.y, acc[i][1]);
                    acc[i][2] = fmaf(av, w0.z, acc[i][2]);
                    acc[i][3] = fmaf(av, w0.w, acc[i][3]);
                    acc[i][4] = fmaf(av, w1.x, acc[i][4]);
                    acc[i][5] = fmaf(av, w1.y, acc[i][5]);
                    acc[i][6] = fmaf(av, w1.z, acc[i][6]);
                    acc[i][7] = fmaf(av, w1.w, acc[i][7]);
                }
            }
        }
        const float* bias = (const float*)(smem + SM_BIAS) + tc * 8;
#pragma unroll
        for (int i = 0; i < 4; i++) {
            int r = tile0 + h * 64 + tr + i * 16;
            if (r < n) {
                float* o = out + (size_t)r * 128 + tc * 8;
#pragma unroll
                for (int c = 0; c < 8; c++) o[c] = acc[i][c] + bias[c];
            }
        }
    }
#endif
}

// ---------------- 4) z pass: z[r] += p2[c] over COO rows -------------------
__global__ void z_kernel(const int* __restrict__ idx, int nnz, int hA, int hB) {
    int j = blockIdx.x * blockDim.x + threadIdx.x;
    if (j >= nnz) return;
    int r = idx[j], c = idx[nnz + j];
    atomicAdd(&g_z[hA * N1C + r], g_p2[hA * N1C + c]);
    if (hB >= 0) atomicAdd(&g_z[hB * N1C + r], g_p2[hB * N1C + c]);
}

// ---------------- 5) dual-head direct-normalized scatter (shared idx) ------
// H[r] += p2A[c]/zA[r] * hA[c] + p2B[c]/zB[r] * hB[c]   (2 edges / warp)
__global__ void att_scatter2_kernel(const int* __restrict__ idx, int nnz, int hA, int hB,
                                    const float* __restrict__ Xh, float* __restrict__ H) {
    int warp = (blockIdx.x * blockDim.x + threadIdx.x) >> 5;
    int lane = threadIdx.x & 31;
    int j = warp * 2 + (lane >> 4);
    int l = lane & 15;
    if (j >= nnz) return;
    int r = idx[j], c = idx[nnz + j];
    float wA = __fdividef(g_p2[hA * N1C + c], g_z[hA * N1C + r]);
    float wB = __fdividef(g_p2[hB * N1C + c], g_z[hB * N1C + r]);
    float4 hA4 = *(const float4*)(Xh + (size_t)c * 128 + l * 4);
    float4 hB4 = *(const float4*)(Xh + (size_t)c * 128 + 64 + l * 4);
    float4 v;
    v.x = wA * hA4.x + wB * hB4.x;
    v.y = wA * hA4.y + wB * hB4.y;
    v.z = wA * hA4.z + wB * hB4.z;
    v.w = wA * hA4.w + wB * hB4.w;
    atomicAdd((float4*)(H + (size_t)r * 64 + l * 4), v);
}

// ---------------- 6) single-head direct-normalized scatter -----------------
__global__ void att_scatter1_kernel(const int* __restrict__ idx, int nnz, int head,
                                    const float* __restrict__ Xh, float* __restrict__ H) {
    int warp = (blockIdx.x * blockDim.x + threadIdx.x) >> 5;
    int lane = threadIdx.x & 31;
    int j = warp * 2 + (lane >> 4);
    int l = lane & 15;
    if (j >= nnz) return;
    int r = idx[j], c = idx[nnz + j];
    float w = __fdividef(g_p2[head * N1C + c], g_z[head * N1C + r]);
    int hoff = (head & 1) * 64;
    float4 hv = *(const float4*)(Xh + (size_t)c * 128 + hoff + l * 4);
    float4 v; v.x = w * hv.x; v.y = w * hv.y; v.z = w * hv.z; v.w = w * hv.w;
    atomicAdd((float4*)(H + (size_t)r * 64 + l * 4), v);
}

// ---------------- 7) COO spmm with fused PReLU on src: dst += val*prelu(src)
__global__ void spmm_kernel(const int* __restrict__ idx, const float* __restrict__ vals,
                            int nnz, const float* __restrict__ src, float* __restrict__ dst,
                            const float* __restrict__ pw) {
    int warp = (blockIdx.x * blockDim.x + threadIdx.x) >> 5;
    int lane = threadIdx.x & 31;
    int j = warp * 2 + (lane >> 4);
    int l = lane & 15;
    if (j >= nnz) return;
    int r = idx[j], c = idx[nnz + j];
    float val = vals[j];
    float p = pw[0];
    float4 x = *(const float4*)(src + (size_t)c * 64 + l * 4);
    x.x = (x.x >= 0.f) ? x.x : p * x.x;
    x.y = (x.y >= 0.f) ? x.y : p * x.y;
    x.z = (x.z >= 0.f) ? x.z : p * x.z;
    x.w = (x.w >= 0.f) ? x.w : p * x.w;
    float4 v; v.x = val * x.x; v.y = val * x.y; v.z = val * x.z; v.w = val * x.w;
    atomicAdd((float4*)(dst + (size_t)r * 64 + l * 4), v);
}

// ---------------- 8) fused B1 spmm: S1 += val*prelu(H1[c]); V += val*U[c] --
__global__ void spmm_b1_fused_kernel(const int* __restrict__ idx, const float* __restrict__ vals,
                                     int nnz, const float* __restrict__ pw) {
    int warp = (blockIdx.x * blockDim.x + threadIdx.x) >> 5;
    int lane = threadIdx.x & 31;
    int j = warp * 2 + (lane >> 4);
    int l = lane & 15;
    if (j >= nnz) return;
    int r = idx[j], c = idx[nnz + j];
    float val = vals[j];
    float p = pw[0];
    if (l == 0) atomicAdd(&g_tsum[r], val);
    float4 x1 = *(const float4*)(g_H1 + (size_t)c * 64 + l * 4);
    x1.x = (x1.x >= 0.f) ? x1.x : p * x1.x;
    x1.y = (x1.y >= 0.f) ? x1.y : p * x1.y;
    x1.z = (x1.z >= 0.f) ? x1.z : p * x1.z;
    x1.w = (x1.w >= 0.f) ? x1.w : p * x1.w;
    float4 xu = *(const float4*)(g_U  + (size_t)c * 64 + l * 4);
    float4 v1; v1.x = val * x1.x; v1.y = val * x1.y; v1.z = val * x1.z; v1.w = val * x1.w;
    float4 vu; vu.x = val * xu.x; vu.y = val * xu.y; vu.z = val * xu.z; vu.w = val * xu.w;
    atomicAdd((float4*)(g_S1 + (size_t)r * 64 + l * 4), v1);
    atomicAdd((float4*)(g_V  + (size_t)r * 64 + l * 4), vu);
}

// ---------------- 9) final: out = (prelu(H0) + S1 + V@triW + tsum*trib)/3 --
__global__ void __launch_bounds__(256)
final_kernel(const float* __restrict__ triW, const float* __restrict__ trib,
             float* __restrict__ out, int n0, const float* __restrict__ pw) {
    __shared__ float sT[64 * 64];
    int t = threadIdx.x;
#pragma unroll
    for (int q = 0; q < 16; q++) sT[q * 256 + t] = triW[q * 256 + t];
    __syncthreads();
    int gw = blockIdx.x * 8 + (t >> 5);
    int lane = t & 31;
    if (gw >= n0) return;
    float p = pw[0];
    float2 v = *(const float2*)(g_V + (size_t)gw * 64 + lane * 2);
    float2 o; o.x = 0.f; o.y = 0.f;
#pragma unroll
    for (int k = 0; k < 64; k++) {
        float vk = __shfl_sync(0xffffffffu, (k & 1) ? v.y : v.x, k >> 1);
        float2 tw = *(const float2*)(sT + k * 64 + lane * 2);
        o.x = fmaf(vk, tw.x, o.x);
        o.y = fmaf(vk, tw.y, o.y);
    }
    float2 h0 = *(const float2*)(g_H0 + (size_t)gw * 64 + lane * 2);
    h0.x = (h0.x >= 0.f) ? h0.x : p * h0.x;
    h0.y = (h0.y >= 0.f) ? h0.y : p * h0.y;
    float2 s1 = *(const float2*)(g_S1 + (size_t)gw * 64 + lane * 2);
    float ts = g_tsum[gw];
    float2 tb = *(const float2*)(trib + lane * 2);
    float2 r;
    r.x = (h0.x + s1.x + o.x + ts * tb.x) * (1.f / 3.f);
    r.y = (h0.y + s1.y + o.y + ts * tb.y) * (1.f / 3.f);
    *(float2*)(out + (size_t)gw * 64 + lane * 2) = r;
}

// ======================== host launcher ====================================
static inline void* symaddr(const void* sym) {
    void* p = nullptr;
    cudaGetSymbolAddress(&p, sym);
    return p;
}

extern "C" void kernel_launch(void* const* d_in, const int* in_sizes, int n_in,
                              void* d_out, int out_size) {
    const float* X0  = (const float*)d_in[0];
    const int*   E1  = (const int*)d_in[1];
    const int*   T2  = (const int*)d_in[2];
    const int*   L0  = (const int*)d_in[3];
    const int*   L1a = (const int*)d_in[4];
    const int*   L1b = (const int*)d_in[5];
    const int*   L2  = (const int*)d_in[6];
    const int*   B1i = (const int*)d_in[7];
    const float* B1v = (const float*)d_in[8];
    const int*   B2i = (const int*)d_in[9];
    const float* B2v = (const float*)d_in[10];
    const float* W   = (const float*)d_in[11];
    const float* b   = (const float*)d_in[12];
    const float* a2w = (const float*)d_in[15];
    const float* a2b = (const float*)d_in[16];
    const float* pw  = (const float*)d_in[17];
    const float* triW = (const float*)d_in[18];
    const float* trib = (const float*)d_in[19];

    int n0 = in_sizes[0] / FINC;
    int n1 = in_sizes[1] / 2;
    int n2 = in_sizes[2] / 3;
    int nnz0  = in_sizes[3] / 2;
    int nnz1a = in_sizes[4] / 2;
    int nnz1b = in_sizes[5] / 2;
    int nnz2  = in_sizes[6] / 2;
    int nb1 = in_sizes[8];
    int nb2 = in_sizes[10];

    float* Xh0 = (float*)symaddr(g_Xh0);
    float* Xh1 = (float*)symaddr(g_Xh1);
    float* Xh2 = (float*)symaddr(g_Xh2);
    float* H0  = (float*)symaddr(g_H0);
    float* H1  = (float*)symaddr(g_H1);
    float* H2  = (float*)symaddr(g_H2);
    float* S1  = (float*)symaddr(g_S1);
    float* U   = (float*)symaddr(g_U);
    float* V   = (float*)symaddr(g_V);
    float* tsum = (float*)symaddr(g_tsum);
    void*  z   = symaddr(g_z);

    static bool attr_set = false;
    if (!attr_set) {
        cudaFuncSetAttribute(mma_feat_kernel,
                             cudaFuncAttributeMaxDynamicSharedMemorySize, SMEM_TOTAL);
        attr_set = true;
    }

    // zero accumulators (graph-capturable memset nodes)
    cudaMemsetAsync(H0, 0, sizeof(float) * (size_t)n0 * 64);
    cudaMemsetAsync(H1, 0, sizeof(float) * (size_t)n1 * 64);
    cudaMemsetAsync(H2, 0, sizeof(float) * (size_t)n2 * 64);
    cudaMemsetAsync(S1, 0, sizeof(float) * (size_t)n0 * 64);
    cudaMemsetAsync(U,  0, sizeof(float) * (size_t)n1 * 64);
    cudaMemsetAsync(V,  0, sizeof(float) * (size_t)n0 * 64);
    cudaMemsetAsync(tsum, 0, sizeof(float) * (size_t)n0);
    cudaMemsetAsync(z,  0, sizeof(float) * 6 * N1C);

    // 1) pack bits, 2) pack weights (both formats)
    pack_bits_kernel<<<(n0 * 32 + 255) / 256, 256>>>(X0, n0);
    pack_Wt_kernel<<<(3 * 8 * 128 * 64 + 255) / 256, 256>>>(W, b);
    pack_W_kernel<<<(3 * 512 * 128 + 255) / 256, 256>>>(W);

    // 3) three feature GEMMs (two heads packed per level; p2 fused in epilogue)
    mma_feat_kernel<<<(n0 + 127) / 128, 256, SMEM_TOTAL>>>(0, 0, n0, E1, Xh0, a2w, a2b);
    mma_feat_kernel<<<(n1 + 127) / 128, 256, SMEM_TOTAL>>>(1, 1, n1, E1, Xh1, a2w, a2b);
    mma_feat_kernel<<<(n2 + 127) / 128, 256, SMEM_TOTAL>>>(2, 2, n2, T2, Xh2, a2w, a2b);

    // 4) softmax denominators
    z_kernel<<<(nnz0 + 255) / 256, 256>>>(L0, nnz0, 0, 1);
    z_kernel<<<(nnz1a + 255) / 256, 256>>>(L1a, nnz1a, 2, -1);
    z_kernel<<<(nnz1b + 255) / 256, 256>>>(L1b, nnz1b, 3, -1);
    z_kernel<<<(nnz2 + 255) / 256, 256>>>(L2, nnz2, 4, 5);

    // 5) direct-normalized attention scatter into 64-wide H
    att_scatter2_kernel<<<(nnz0 + 15) / 16, 256>>>(L0, nnz0, 0, 1, Xh0, H0);
    att_scatter1_kernel<<<(nnz1a + 15) / 16, 256>>>(L1a, nnz1a, 2, Xh1, H1);
    att_scatter1_kernel<<<(nnz1b + 15) / 16, 256>>>(L1b, nnz1b, 3, Xh1, H1);
    att_scatter2_kernel<<<(nnz2 + 15) / 16, 256>>>(L2, nnz2, 4, 5, Xh2, H2);

    // 6) boundary spmms (PReLU fused into the gathers)
    spmm_kernel<<<(nb2 + 15) / 16, 256>>>(B2i, B2v, nb2, H2, U, pw);
    spmm_b1_fused_kernel<<<(nb1 + 15) / 16, 256>>>(B1i, B1v, nb1, pw);

    // 7) combine (PReLU on H0 fused)
    final_kernel<<<(n0 + 7) / 8, 256>>>(triW, trib, (float*)d_out, n0, pw);
}